// round 13
// baseline (speedup 1.0000x reference)
#include <cuda_runtime.h>
#include <math.h>

#define N_NODES 5000
#define NBINS 50
#define KNN 16
#define SLOPE 0.01f
#define PH 129   // hidden-buffer pitch (129 mod 32 = 1 -> conflict-free)

// ---------------- device scratch ----------------
__device__ float g_h[N_NODES * 12];     // nn1 output (pre-leaky)
__device__ int   g_bin[N_NODES];
__device__ int   g_sorted[N_NODES];     // stable argsort of g_bin
__device__ float g_hf[N_NODES * 32];    // post-conv, post-leaky features

__device__ __forceinline__ float lrelu(float v) { return v > 0.f ? v : SLOPE * v; }

__device__ __forceinline__ unsigned long long pack2(float a, float b) {
    unsigned long long r;
    asm("mov.b64 %0, {%1, %2};" : "=l"(r) : "r"(__float_as_uint(a)), "r"(__float_as_uint(b)));
    return r;
}
__device__ __forceinline__ void unpack2(unsigned long long p, float& a, float& b) {
    unsigned int x, y;
    asm("mov.b64 {%0, %1}, %2;" : "=r"(x), "=r"(y) : "l"(p));
    a = __uint_as_float(x); b = __uint_as_float(y);
}
__device__ __forceinline__ unsigned long long ffma2(unsigned long long a, unsigned long long b, unsigned long long c) {
    unsigned long long d;
    asm("fma.rn.f32x2 %0, %1, %2, %3;" : "=l"(d) : "l"(a), "l"(b), "l"(c));
    return d;
}

// ---------------- MLP machinery -------------------------------------------
// 512 threads, 32 rows/block, grid = 157, 2 blocks/SM -> ONE wave.
// warp w16 = tid>>5: cg = w16 & 7 (16-col slice, j0 = cg*16), kh = w16>>3
// (K-half). lane = row. Partner partials are exchanged THROUGH H (no Pbuf):
// kh=1 stores raw partial to H; bar; kh=0 adds bias+partial, activates.

template <int IN, int OUT, int P3>
__device__ __forceinline__ void stage_net(
    const float* __restrict__ W1, const float* __restrict__ b1,
    const float* __restrict__ W2, const float* __restrict__ b2,
    const float* __restrict__ W3, const float* __restrict__ b3,
    float* Ws1, float* Ws2, float* Ws3, float* b1s, float* b2s, float* b3s, int tid)
{
    for (int idx = tid; idx < IN * 128; idx += 512) {
        const int k = idx >> 7, j = idx & 127;
        Ws1[idx] = (j < 125) ? W1[k * 125 + j] : 0.f;
    }
    for (int idx = tid; idx < 125 * 128; idx += 512) {
        const int k = idx >> 7, j = idx & 127;
        Ws2[idx] = (j < 125) ? W2[k * 125 + j] : 0.f;
    }
    for (int idx = tid; idx < 125 * P3; idx += 512) {
        const int k = idx / P3, o = idx % P3;
        Ws3[idx] = (o < OUT) ? W3[k * OUT + o] : 0.f;
    }
    if (tid < 128) {
        b1s[tid] = (tid < 125) ? b1[tid] : 0.f;
        b2s[tid] = (tid < 125) ? b2[tid] : 0.f;
    } else if (tid < 144) {
        const int o = tid - 128;
        b3s[o] = (o < OUT) ? b3[o] : 0.f;
    }
}

template <int K0, int K1>
__device__ __forceinline__ void dense_range(const float* __restrict__ Ws,
                                            const float* __restrict__ xrow,
                                            int j0, unsigned long long acc[8])
{
    #pragma unroll 5
    for (int k = K0; k < K1; k++) {
        const float xv = xrow[k];
        const unsigned long long xx = pack2(xv, xv);
        const ulonglong2* wp = (const ulonglong2*)(Ws + k * 128 + j0);
        const ulonglong2 wa = wp[0], wb = wp[1], wc = wp[2], wd = wp[3];
        acc[0] = ffma2(xx, wa.x, acc[0]); acc[1] = ffma2(xx, wa.y, acc[1]);
        acc[2] = ffma2(xx, wb.x, acc[2]); acc[3] = ffma2(xx, wb.y, acc[3]);
        acc[4] = ffma2(xx, wc.x, acc[4]); acc[5] = ffma2(xx, wc.y, acc[5]);
        acc[6] = ffma2(xx, wd.x, acc[6]); acc[7] = ffma2(xx, wd.y, acc[7]);
    }
}

__device__ __forceinline__ void zero8(unsigned long long a[8]) {
    #pragma unroll
    for (int m = 0; m < 8; m++) a[m] = pack2(0.f, 0.f);
}
__device__ __forceinline__ void store_partial(unsigned long long acc[8], float* dst) {
    #pragma unroll
    for (int m = 0; m < 8; m++) {
        float a, b; unpack2(acc[m], a, b);
        dst[2 * m] = a; dst[2 * m + 1] = b;
    }
}
// Pb may alias Hd (read-then-write per element is safe)
__device__ __forceinline__ void combine_act(unsigned long long acc[8], const float* __restrict__ bS,
                                            const float* Pb, float* Hd, int j0)
{
    #pragma unroll
    for (int m = 0; m < 8; m++) {
        float a, b; unpack2(acc[m], a, b);
        const int j = j0 + 2 * m;
        const float b0 = (j < 125) ? bS[j] : 0.f;
        const float b1 = (j + 1 < 125) ? bS[j + 1] : 0.f;
        const float p0 = Pb[j], p1 = Pb[j + 1];
        Hd[j]     = lrelu(b0 + a + p0);
        Hd[j + 1] = lrelu(b1 + b + p1);
    }
}

// 3-layer net, K-split; partner partials through H. Outputs on kh==0 warps.
template <int IN, int OUT, int P3>
__device__ __forceinline__ void run_mlp_split(
    const float* __restrict__ xrow,
    const float* Ws1, const float* Ws2, const float* Ws3,
    const float* b1s, const float* b2s, const float* b3s,
    float* H, float* Obuf,
    int lane, int j0, int cg, int kh, float& o1, float& o2)
{
    unsigned long long acc[8];
    float* Hrow = H + lane * PH;

    // ---- layer 1 ----
    zero8(acc);
    if (kh == 0) dense_range<0, IN / 2>(Ws1, xrow, j0, acc);
    else         dense_range<IN / 2, IN>(Ws1, xrow, j0, acc);
    if (kh == 1) store_partial(acc, Hrow + j0);
    __syncthreads();
    if (kh == 0) combine_act(acc, b1s, Hrow, Hrow, j0);
    __syncthreads();

    // ---- layer 2 (K=125) ----
    zero8(acc);
    if (kh == 0) dense_range<0, 63>(Ws2, Hrow, j0, acc);
    else         dense_range<63, 125>(Ws2, Hrow, j0, acc);
    __syncthreads();                     // all H reads complete before overwrite
    if (kh == 1) store_partial(acc, Hrow + j0);
    __syncthreads();
    if (kh == 0) combine_act(acc, b2s, Hrow, Hrow, j0);
    __syncthreads();

    // ---- layer 3 ----
    const bool c1 = (cg < OUT);
    const bool c2 = (OUT > 8) && (cg + 8 < OUT);
    float a1 = 0.f, a2 = 0.f;
    if (kh == 0) {
        #pragma unroll 7
        for (int k = 0; k < 63; k++) {
            const float hv = Hrow[k];
            if (c1) a1 += hv * Ws3[k * P3 + cg];
            if (c2) a2 += hv * Ws3[k * P3 + cg + 8];
        }
    } else {
        #pragma unroll 7
        for (int k = 63; k < 125; k++) {
            const float hv = Hrow[k];
            if (c1) a1 += hv * Ws3[k * P3 + cg];
            if (c2) a2 += hv * Ws3[k * P3 + cg + 8];
        }
    }
    if (kh == 1) {
        if (c1) Obuf[lane * 17 + cg] = a1;
        if (c2) Obuf[lane * 17 + cg + 8] = a2;
    }
    __syncthreads();
    o1 = 0.f; o2 = 0.f;
    if (kh == 0) {
        if (c1) o1 = b3s[cg] + a1 + Obuf[lane * 17 + cg];
        if (c2) o2 = b3s[cg + 8] + a2 + Obuf[lane * 17 + cg + 8];
    }
}

// ---------------- nn1 + fused LSH binning --------------------------------
__global__ __launch_bounds__(512, 2)
void nn1_kernel(const float* __restrict__ x,
                const float* __restrict__ W1, const float* __restrict__ b1,
                const float* __restrict__ W2, const float* __restrict__ b2,
                const float* __restrict__ W3, const float* __restrict__ b3,
                const float* __restrict__ cb)
{
    extern __shared__ float sm[];
    float* Ws1 = sm;                      // 12*128 = 1536
    float* Ws2 = Ws1 + 1536;              // 16000
    float* Ws3 = Ws2 + 16000;             // 125*16 = 2000
    float* b1s = Ws3 + 2000;              // 128
    float* b2s = b1s + 128;               // 128
    float* b3s = b2s + 128;               // 16
    float* H    = b3s + 16;               // 32*PH = 4128
    float* Obuf = H + 32 * PH;            // 544
    float* cbs  = Obuf + 544;             // 300
    float* xinS = cbs + 300;              // 416
    float* HoutS = xinS + 416;            // 416

    const int tid = threadIdx.x;
    stage_net<12, 12, 16>(W1, b1, W2, b2, W3, b3, Ws1, Ws2, Ws3, b1s, b2s, b3s, tid);
    for (int idx = tid; idx < 300; idx += 512) {
        const int k = idx / 25, c = idx % 25;
        cbs[idx] = cb[k * 100 + c];
    }
    for (int idx = tid; idx < 32 * 12; idx += 512) {
        const int r = idx / 12, c = idx % 12;
        const int row = blockIdx.x * 32 + r;
        xinS[r * 13 + c] = (row < N_NODES) ? x[row * 12 + c] : 0.f;
    }
    __syncthreads();

    const int lane = tid & 31;
    const int w16  = tid >> 5;
    const int cg   = w16 & 7;
    const int kh   = w16 >> 3;
    const int j0   = cg * 16;
    const int row  = blockIdx.x * 32 + lane;
    const bool valid = row < N_NODES;

    float o1, o2;
    run_mlp_split<12, 12, 16>(xinS + lane * 13, Ws1, Ws2, Ws3, b1s, b2s, b3s,
                              H, Obuf, lane, j0, cg, kh, o1, o2);

    if (kh == 0) {
        if (valid) g_h[row * 12 + cg] = o1;
        HoutS[lane * 13 + cg] = o1;
        if (cg < 4) {
            if (valid) g_h[row * 12 + 8 + cg] = o2;
            HoutS[lane * 13 + 8 + cg] = o2;
        }
    }
    __syncthreads();

    if (tid < 32) {
        const int r2 = blockIdx.x * 32 + tid;
        if (r2 < N_NODES) {
            float hr[12];
            #pragma unroll
            for (int k = 0; k < 12; k++) hr[k] = HoutS[tid * 13 + k];
            float mul[25];
            #pragma unroll
            for (int c = 0; c < 25; c++) {
                float s = 0.f;
                #pragma unroll
                for (int k = 0; k < 12; k++) s += hr[k] * cbs[k * 25 + c];
                mul[c] = s;
            }
            float best = -3.4e38f; int bi = 0;
            #pragma unroll
            for (int c = 0; c < 50; c++) {
                const float v = (c < 25) ? mul[c] : -mul[c - 25];
                if (v > best) { best = v; bi = c; }   // first-max: jnp.argmax
            }
            g_bin[r2] = bi;
        }
    }
}

// ---------------- nn2 (g_hf -> cand_ids) + passthrough copies -------------
__global__ __launch_bounds__(512, 2)
void nn2_kernel(const float* __restrict__ W1, const float* __restrict__ b1,
                const float* __restrict__ W2, const float* __restrict__ b2,
                const float* __restrict__ W3, const float* __restrict__ b3,
                float* __restrict__ cand_ids,
                const float* __restrict__ ygen_id, float* __restrict__ out_yid,
                const float* __restrict__ ygen,    float* __restrict__ out_yg)
{
    extern __shared__ float sm[];
    float* Ws1 = sm;                      // 32*128 = 4096
    float* Ws2 = Ws1 + 4096;              // 16000
    float* Ws3 = Ws2 + 16000;             // 125*8 = 1000
    float* b1s = Ws3 + 1000;              // 128
    float* b2s = b1s + 128;
    float* b3s = b2s + 128;               // 16
    float* H    = b3s + 16;               // 4128
    float* Obuf = H + 32 * PH;            // 544
    float* xinS = Obuf + 544;             // 32*33 = 1056

    const int tid = threadIdx.x;
    const int gt  = blockIdx.x * 512 + tid;
    if (gt < 30000) { out_yid[gt] = ygen_id[gt]; out_yg[gt] = ygen[gt]; }

    stage_net<32, 6, 8>(W1, b1, W2, b2, W3, b3, Ws1, Ws2, Ws3, b1s, b2s, b3s, tid);
    for (int idx = tid; idx < 32 * 32; idx += 512) {
        const int r = idx >> 5, c = idx & 31;
        const int row = blockIdx.x * 32 + r;
        xinS[r * 33 + c] = (row < N_NODES) ? g_hf[row * 32 + c] : 0.f;
    }
    __syncthreads();

    const int lane = tid & 31;
    const int w16  = tid >> 5;
    const int cg   = w16 & 7;
    const int kh   = w16 >> 3;
    const int j0   = cg * 16;
    const int row  = blockIdx.x * 32 + lane;

    float o1, o2;
    run_mlp_split<32, 6, 8>(xinS + lane * 33, Ws1, Ws2, Ws3, b1s, b2s, b3s,
                            H, Obuf, lane, j0, cg, kh, o1, o2);

    if (kh == 0 && cg < 6 && row < N_NODES) cand_ids[row * 6 + cg] = o1;
}

// ---------------- nn3 ([g_hf, cand_ids] -> cand_p4) -----------------------
__global__ __launch_bounds__(512, 2)
void nn3_kernel(const float* __restrict__ W1, const float* __restrict__ b1,
                const float* __restrict__ W2, const float* __restrict__ b2,
                const float* __restrict__ W3, const float* __restrict__ b3,
                const float* __restrict__ cand_ids, float* __restrict__ cand_p4)
{
    extern __shared__ float sm[];
    float* Ws1 = sm;                      // 38*128 = 4864
    float* Ws2 = Ws1 + 4864;              // 16000
    float* Ws3 = Ws2 + 16000;             // 1000
    float* b1s = Ws3 + 1000;              // 128
    float* b2s = b1s + 128;
    float* b3s = b2s + 128;               // 16
    float* H    = b3s + 16;               // 4128
    float* Obuf = H + 32 * PH;            // 544
    float* xinS = Obuf + 544;             // 32*39 = 1248

    const int tid = threadIdx.x;
    stage_net<38, 6, 8>(W1, b1, W2, b2, W3, b3, Ws1, Ws2, Ws3, b1s, b2s, b3s, tid);
    for (int idx = tid; idx < 32 * 32; idx += 512) {
        const int r = idx >> 5, c = idx & 31;
        const int row = blockIdx.x * 32 + r;
        xinS[r * 39 + c] = (row < N_NODES) ? g_hf[row * 32 + c] : 0.f;
    }
    for (int idx = tid; idx < 32 * 6; idx += 512) {
        const int r = idx / 6, c = idx % 6;
        const int row = blockIdx.x * 32 + r;
        xinS[r * 39 + 32 + c] = (row < N_NODES) ? cand_ids[row * 6 + c] : 0.f;
    }
    __syncthreads();

    const int lane = tid & 31;
    const int w16  = tid >> 5;
    const int cg   = w16 & 7;
    const int kh   = w16 >> 3;
    const int j0   = cg * 16;
    const int row  = blockIdx.x * 32 + lane;

    float o1, o2;
    run_mlp_split<38, 6, 8>(xinS + lane * 39, Ws1, Ws2, Ws3, b1s, b2s, b3s,
                            H, Obuf, lane, j0, cg, kh, o1, o2);

    if (kh == 0 && cg < 6 && row < N_NODES) cand_p4[row * 6 + cg] = o1;
}

// ---------------- stable counting-sort (verbatim) --------------------------
__global__ __launch_bounds__(256, 1) void sort_kernel()
{
    __shared__ int cB[8], cL[8];
    const int b = blockIdx.x;
    const int w = threadIdx.x >> 5, lane = threadIdx.x & 31;
    const int beg = w * 625, end = beg + 625;

    int nB = 0, nL = 0;
    for (int i0 = beg; i0 < end; i0 += 32) {
        const int i = i0 + lane;
        const bool inr = i < end;
        const int bv = inr ? g_bin[i] : 0x7fffffff;
        nB += __popc(__ballot_sync(0xffffffffu, inr && bv == b));
        nL += __popc(__ballot_sync(0xffffffffu, inr && bv <  b));
    }
    if (lane == 0) { cB[w] = nB; cL[w] = nL; }
    __syncthreads();

    int off = 0;
    #pragma unroll
    for (int q = 0; q < 8; q++) off += cL[q];
    for (int q = 0; q < w; q++) off += cB[q];

    for (int i0 = beg; i0 < end; i0 += 32) {
        const int i = i0 + lane;
        const bool inr = i < end;
        const int bv = inr ? g_bin[i] : 0x7fffffff;
        const bool p = inr && bv == b;
        const unsigned m = __ballot_sync(0xffffffffu, p);
        if (p) g_sorted[off + __popc(m & ((1u << lane) - 1u))] = i;
        off += __popc(m);
    }
}

// ---------------- per-chunk graph kernel (verbatim) -----------------------
__global__ __launch_bounds__(512, 1)
void bin_kernel(const float* __restrict__ gcnW, const float* __restrict__ gcnb,
                const float* __restrict__ Wrel, const float* __restrict__ brel,
                const float* __restrict__ Wroot)
{
    extern __shared__ float sm[];
    float* P    = sm;                   // 100 x 13
    float* D    = P + 1300;             // 100 x 101
    float* HW   = D + 10100;            // 100 x 33
    float* GC   = HW + 3300;
    float* AGG  = GC + 3300;
    float* Ew   = AGG + 3300;           // 1600
    float* coef = Ew + 1600;            // 1600
    float* degf = coef + 1600;          // 100
    float* gws  = degf + 100;           // 384
    float* gbs  = gws + 384;            // 32
    float* wrs  = gbs + 32;             // 1024
    float* wts  = wrs + 1024;           // 1024
    float* brs  = wts + 1024;           // 32
    int* sids  = (int*)(brs + 32);      // 100
    int* Ed    = sids + 100;            // 1600
    int* roff  = Ed + 1600;             // 128
    int* cnt   = roff + 128;            // 100
    int* rlist = cnt + 100;             // 1600

    const int tid = threadIdx.x;
    const int b = blockIdx.x;

    if (tid < 100) sids[tid] = g_sorted[b * 100 + tid];
    for (int idx = tid; idx < 384; idx += 512) gws[idx] = gcnW[idx];
    for (int idx = tid; idx < 1024; idx += 512) { wrs[idx] = Wrel[idx]; wts[idx] = Wroot[idx]; }
    if (tid < 32) { gbs[tid] = gcnb[tid]; brs[tid] = brel[tid]; }
    if (tid < 128) roff[tid] = 0;
    if (tid < 100) cnt[tid] = 0;
    __syncthreads();
    for (int idx = tid; idx < 1200; idx += 512) {
        const int i = idx / 12, k = idx % 12;
        P[i * 13 + k] = g_h[sids[i] * 12 + k];
    }
    __syncthreads();

    for (int p = tid; p < 10000; p += 512) {
        const int i = p / 100, j = p % 100;
        if (j < i) continue;
        float s = 0.f;
        #pragma unroll
        for (int k = 0; k < 12; k++) s += P[i * 13 + k] * P[j * 13 + k];
        const float v = 1.f / (1.f + __expf(-s));
        D[i * 101 + j] = v;
        D[j * 101 + i] = v;
    }
    __syncthreads();

    // top-16 per row: streaming insertion (stable: strict >, earlier index wins ties)
    if (tid < 100) {
        const float* Drow = D + tid * 101;
        float tv[16]; int tj[16];
        #pragma unroll
        for (int s = 0; s < 16; s++) { tv[s] = -1.f; tj[s] = 0; }
        for (int j = 0; j < 100; j++) {
            const float v = Drow[j];
            if (v > tv[15]) {
                #pragma unroll
                for (int s = 15; s >= 1; s--) {
                    const bool up = (v > tv[s - 1]);
                    const bool here = !up && (v > tv[s]);
                    tv[s] = up ? tv[s - 1] : (here ? v : tv[s]);
                    tj[s] = up ? tj[s - 1] : (here ? j : tj[s]);
                }
                if (v > tv[0]) { tv[0] = v; tj[0] = j; }
            }
        }
        #pragma unroll
        for (int s = 0; s < 16; s++) { Ew[tid * 16 + s] = tv[s]; Ed[tid * 16 + s] = tj[s]; }
    }
    __syncthreads();

    for (int e = tid; e < 1600; e += 512) atomicAdd(&roff[Ed[e] + 1], 1);
    __syncthreads();
    for (int d = 1; d < 128; d <<= 1) {
        int v = 0;
        if (tid < 101 && tid >= d) v = roff[tid - d];
        __syncthreads();
        if (tid < 101) roff[tid] += v;
        __syncthreads();
    }
    for (int e = tid; e < 1600; e += 512) {
        const int d = Ed[e];
        const int slot = atomicAdd(&cnt[d], 1);
        rlist[roff[d] + slot] = e;
    }
    __syncthreads();

    if (tid < 100) {
        float dg = 1.f;
        const int q1 = roff[tid + 1];
        for (int q = roff[tid]; q < q1; q++) dg += Ew[rlist[q]];
        degf[tid] = 1.f / sqrtf(dg);
    }
    __syncthreads();

    for (int idx = tid; idx < 1300; idx += 512) P[idx] = lrelu(P[idx]);
    for (int e = tid; e < 1600; e += 512) coef[e] = Ew[e] * degf[e >> 4];
    __syncthreads();

    const int f  = tid & 31;
    const int c0 = tid >> 5;

    for (int c = c0; c < 100; c += 16) {
        float a = 0.f;
        #pragma unroll
        for (int k = 0; k < 12; k++) a += P[c * 13 + k] * gws[k * 32 + f];
        HW[c * 33 + f] = a;
    }
    __syncthreads();

    for (int c = c0; c < 100; c += 16) {
        float a = 0.f;
        const int q1 = roff[c + 1];
        for (int q = roff[c]; q < q1; q++) {
            const int e = rlist[q];
            a += coef[e] * HW[(e >> 4) * 33 + f];
        }
        const float dc = degf[c];
        GC[c * 33 + f] = gbs[f] + dc * a + dc * dc * HW[c * 33 + f];
    }
    __syncthreads();

    for (int c = c0; c < 100; c += 16) {
        float a = 0.f;
        const int q1 = roff[c + 1];
        for (int q = roff[c]; q < q1; q++) {
            const int e = rlist[q];
            a += Ew[e] * GC[(e >> 4) * 33 + f];
        }
        AGG[c * 33 + f] = a;
    }
    __syncthreads();

    for (int c = c0; c < 100; c += 16) {
        float a = brs[f];
        #pragma unroll
        for (int k = 0; k < 32; k++) a += AGG[c * 33 + k] * wrs[k * 32 + f] + GC[c * 33 + k] * wts[k * 32 + f];
        g_hf[sids[c] * 32 + f] = lrelu(a);
    }
}

// ---------------- host launcher ------------------------------------------
static size_t nn1_smem() {
    return (size_t)(1536 + 16000 + 2000 + 272 + 32 * PH + 544 + 300 + 416 + 416) * 4;
}
static size_t nn2_smem() {
    return (size_t)(4096 + 16000 + 1000 + 272 + 32 * PH + 544 + 1056) * 4;
}
static size_t nn3_smem() {
    return (size_t)(4864 + 16000 + 1000 + 272 + 32 * PH + 544 + 1248) * 4;
}
static size_t bin_smem() {
    size_t fl = 1300 + 10100 + 3 * 3300 + 1600 + 1600 + 100 + 384 + 32 + 1024 + 1024 + 32;
    size_t in = 100 + 1600 + 128 + 100 + 1600;
    return (fl + in) * 4;
}

extern "C" void kernel_launch(void* const* d_in, const int* in_sizes, int n_in,
                              void* d_out, int out_size)
{
    const float* x       = (const float*)d_in[0];
    const float* ygen_id = (const float*)d_in[1];
    const float* ygen    = (const float*)d_in[2];
    const float* cb      = (const float*)d_in[3];
    const float* nn1_W1 = (const float*)d_in[4];
    const float* nn1_b1 = (const float*)d_in[5];
    const float* nn1_W2 = (const float*)d_in[6];
    const float* nn1_b2 = (const float*)d_in[7];
    const float* nn1_W3 = (const float*)d_in[8];
    const float* nn1_b3 = (const float*)d_in[9];
    const float* gcn_W  = (const float*)d_in[10];
    const float* gcn_b  = (const float*)d_in[11];
    const float* gc_Wrel  = (const float*)d_in[12];
    const float* gc_brel  = (const float*)d_in[13];
    const float* gc_Wroot = (const float*)d_in[14];
    const float* nn2_W1 = (const float*)d_in[15];
    const float* nn2_b1 = (const float*)d_in[16];
    const float* nn2_W2 = (const float*)d_in[17];
    const float* nn2_b2 = (const float*)d_in[18];
    const float* nn2_W3 = (const float*)d_in[19];
    const float* nn2_b3 = (const float*)d_in[20];
    const float* nn3_W1 = (const float*)d_in[21];
    const float* nn3_b1 = (const float*)d_in[22];
    const float* nn3_W2 = (const float*)d_in[23];
    const float* nn3_b2 = (const float*)d_in[24];
    const float* nn3_W3 = (const float*)d_in[25];
    const float* nn3_b3 = (const float*)d_in[26];

    float* out = (float*)d_out;

    cudaFuncSetAttribute(nn1_kernel, cudaFuncAttributeMaxDynamicSharedMemorySize, (int)nn1_smem());
    cudaFuncSetAttribute(nn2_kernel, cudaFuncAttributeMaxDynamicSharedMemorySize, (int)nn2_smem());
    cudaFuncSetAttribute(nn3_kernel, cudaFuncAttributeMaxDynamicSharedMemorySize, (int)nn3_smem());
    cudaFuncSetAttribute(bin_kernel, cudaFuncAttributeMaxDynamicSharedMemorySize, (int)bin_smem());

    const int grid = (N_NODES + 31) / 32;   // 157 -> one wave at 2 blocks/SM

    nn1_kernel<<<grid, 512, nn1_smem()>>>(x, nn1_W1, nn1_b1, nn1_W2, nn1_b2, nn1_W3, nn1_b3, cb);
    sort_kernel<<<NBINS, 256>>>();
    bin_kernel<<<NBINS, 512, bin_smem()>>>(gcn_W, gcn_b, gc_Wrel, gc_brel, gc_Wroot);
    nn2_kernel<<<grid, 512, nn2_smem()>>>(nn2_W1, nn2_b1, nn2_W2, nn2_b2, nn2_W3, nn2_b3,
                                          out, ygen_id, out + 60000, ygen, out + 90000);
    nn3_kernel<<<grid, 512, nn3_smem()>>>(nn3_W1, nn3_b1, nn3_W2, nn3_b2, nn3_W3, nn3_b3,
                                          out, out + 30000);
}

// round 14
// speedup vs baseline: 1.1675x; 1.1675x over previous
#include <cuda_runtime.h>
#include <math.h>

#define N_NODES 5000
#define NBINS 50
#define KNN 16
#define SLOPE 0.01f
#define PH 129   // hidden-buffer pitch (129 mod 32 = 1 -> conflict-free)

// ---------------- device scratch ----------------
__device__ float g_h[N_NODES * 12];     // nn1 output (pre-leaky)
__device__ int   g_bin[N_NODES];
__device__ int   g_sorted[N_NODES];     // stable argsort of g_bin
__device__ float g_hf[N_NODES * 32];    // post-conv, post-leaky features
__device__ float g_Ew[NBINS * 1600];    // per-bin edge weights (row-major, 16/row)
__device__ int   g_Ed[NBINS * 1600];    // per-bin local dst indices

__device__ __forceinline__ float lrelu(float v) { return v > 0.f ? v : SLOPE * v; }

__device__ __forceinline__ unsigned long long pack2(float a, float b) {
    unsigned long long r;
    asm("mov.b64 %0, {%1, %2};" : "=l"(r) : "r"(__float_as_uint(a)), "r"(__float_as_uint(b)));
    return r;
}
__device__ __forceinline__ void unpack2(unsigned long long p, float& a, float& b) {
    unsigned int x, y;
    asm("mov.b64 {%0, %1}, %2;" : "=r"(x), "=r"(y) : "l"(p));
    a = __uint_as_float(x); b = __uint_as_float(y);
}
__device__ __forceinline__ unsigned long long ffma2(unsigned long long a, unsigned long long b, unsigned long long c) {
    unsigned long long d;
    asm("fma.rn.f32x2 %0, %1, %2, %3;" : "=l"(d) : "l"(a), "l"(b), "l"(c));
    return d;
}

// ---------------- MLP machinery (R12 verbatim) -----------------------------
// 512 threads, 64 rows/block (2 rows per lane: lane and lane+32), grid = 79.
// warp w16 = tid>>5: cg = w16 & 7 (16-col slice, j0 = cg*16), kh = w16>>3
// (K-half). Weights staged in smem. kh=1 stores partials; kh=0 combines.

template <int IN, int OUT, int P3>
__device__ __forceinline__ void stage_net(
    const float* __restrict__ W1, const float* __restrict__ b1,
    const float* __restrict__ W2, const float* __restrict__ b2,
    const float* __restrict__ W3, const float* __restrict__ b3,
    float* Ws1, float* Ws2, float* Ws3, float* b1s, float* b2s, float* b3s, int tid)
{
    for (int idx = tid; idx < IN * 128; idx += 512) {
        const int k = idx >> 7, j = idx & 127;
        Ws1[idx] = (j < 125) ? W1[k * 125 + j] : 0.f;
    }
    for (int idx = tid; idx < 125 * 128; idx += 512) {
        const int k = idx >> 7, j = idx & 127;
        Ws2[idx] = (j < 125) ? W2[k * 125 + j] : 0.f;
    }
    for (int idx = tid; idx < 125 * P3; idx += 512) {
        const int k = idx / P3, o = idx % P3;
        Ws3[idx] = (o < OUT) ? W3[k * OUT + o] : 0.f;
    }
    if (tid < 128) {
        b1s[tid] = (tid < 125) ? b1[tid] : 0.f;
        b2s[tid] = (tid < 125) ? b2[tid] : 0.f;
    } else if (tid < 144) {
        const int o = tid - 128;
        b3s[o] = (o < OUT) ? b3[o] : 0.f;
    }
}

// two-row dense: acc[8] per row, weights loaded once per k
template <int K0, int K1>
__device__ __forceinline__ void dense_range2(const float* __restrict__ Ws,
                                             const float* __restrict__ x0,
                                             const float* __restrict__ x1,
                                             int j0,
                                             unsigned long long accA[8],
                                             unsigned long long accB[8])
{
    #pragma unroll 5
    for (int k = K0; k < K1; k++) {
        const float va = x0[k], vb = x1[k];
        const unsigned long long xa = pack2(va, va);
        const unsigned long long xb = pack2(vb, vb);
        const ulonglong2* wp = (const ulonglong2*)(Ws + k * 128 + j0);
        const ulonglong2 wa = wp[0], wb = wp[1], wc = wp[2], wd = wp[3];
        accA[0] = ffma2(xa, wa.x, accA[0]); accA[1] = ffma2(xa, wa.y, accA[1]);
        accA[2] = ffma2(xa, wb.x, accA[2]); accA[3] = ffma2(xa, wb.y, accA[3]);
        accA[4] = ffma2(xa, wc.x, accA[4]); accA[5] = ffma2(xa, wc.y, accA[5]);
        accA[6] = ffma2(xa, wd.x, accA[6]); accA[7] = ffma2(xa, wd.y, accA[7]);
        accB[0] = ffma2(xb, wa.x, accB[0]); accB[1] = ffma2(xb, wa.y, accB[1]);
        accB[2] = ffma2(xb, wb.x, accB[2]); accB[3] = ffma2(xb, wb.y, accB[3]);
        accB[4] = ffma2(xb, wc.x, accB[4]); accB[5] = ffma2(xb, wc.y, accB[5]);
        accB[6] = ffma2(xb, wd.x, accB[6]); accB[7] = ffma2(xb, wd.y, accB[7]);
    }
}

__device__ __forceinline__ void zero8(unsigned long long a[8]) {
    #pragma unroll
    for (int m = 0; m < 8; m++) a[m] = pack2(0.f, 0.f);
}
__device__ __forceinline__ void store_partial(unsigned long long acc[8], float* dst) {
    #pragma unroll
    for (int m = 0; m < 8; m++) {
        float a, b; unpack2(acc[m], a, b);
        dst[2 * m] = a; dst[2 * m + 1] = b;
    }
}
__device__ __forceinline__ void combine_act(unsigned long long acc[8], const float* __restrict__ bS,
                                            const float* __restrict__ Pb, float* __restrict__ Hd, int j0)
{
    #pragma unroll
    for (int m = 0; m < 8; m++) {
        float a, b; unpack2(acc[m], a, b);
        const int j = j0 + 2 * m;
        const float b0 = (j < 125) ? bS[j] : 0.f;
        const float b1 = (j + 1 < 125) ? bS[j + 1] : 0.f;
        Hd[j]     = lrelu(b0 + a + Pb[j]);
        Hd[j + 1] = lrelu(b1 + b + Pb[j + 1]);
    }
}

// 3-layer net, K-split + 2 rows/lane. x0/x1 = input rows lane / lane+32.
template <int IN, int OUT, int P3>
__device__ __forceinline__ void run_mlp2(
    const float* __restrict__ x0, const float* __restrict__ x1,
    const float* Ws1, const float* Ws2, const float* Ws3,
    const float* b1s, const float* b2s, const float* b3s,
    float* H, float* Pbuf, float* Obuf,
    int lane, int j0, int cg, int kh,
    float& o1A, float& o2A, float& o1B, float& o2B)
{
    unsigned long long accA[8], accB[8];
    float* H0 = H + lane * PH;
    float* H1 = H + (lane + 32) * PH;
    float* P0 = Pbuf + lane * PH;
    float* P1 = Pbuf + (lane + 32) * PH;

    // ---- layer 1 ----
    zero8(accA); zero8(accB);
    if (kh == 0) dense_range2<0, IN / 2>(Ws1, x0, x1, j0, accA, accB);
    else         dense_range2<IN / 2, IN>(Ws1, x0, x1, j0, accA, accB);
    if (kh == 1) { store_partial(accA, P0 + j0); store_partial(accB, P1 + j0); }
    __syncthreads();
    if (kh == 0) { combine_act(accA, b1s, P0, H0, j0); combine_act(accB, b1s, P1, H1, j0); }
    __syncthreads();

    // ---- layer 2 (K=125) ----
    zero8(accA); zero8(accB);
    if (kh == 0) dense_range2<0, 63>(Ws2, H0, H1, j0, accA, accB);
    else         dense_range2<63, 125>(Ws2, H0, H1, j0, accA, accB);
    if (kh == 1) { store_partial(accA, P0 + j0); store_partial(accB, P1 + j0); }
    __syncthreads();
    if (kh == 0) { combine_act(accA, b2s, P0, H0, j0); combine_act(accB, b2s, P1, H1, j0); }
    __syncthreads();

    // ---- layer 3 ----
    const bool c1 = (cg < OUT);
    const bool c2 = (OUT > 8) && (cg + 8 < OUT);
    float a1A = 0.f, a2A = 0.f, a1B = 0.f, a2B = 0.f;
    if (kh == 0) {
        #pragma unroll 7
        for (int k = 0; k < 63; k++) {
            const float hA = H0[k], hB = H1[k];
            if (c1) { a1A += hA * Ws3[k * P3 + cg];     a1B += hB * Ws3[k * P3 + cg]; }
            if (c2) { a2A += hA * Ws3[k * P3 + cg + 8]; a2B += hB * Ws3[k * P3 + cg + 8]; }
        }
    } else {
        #pragma unroll 7
        for (int k = 63; k < 125; k++) {
            const float hA = H0[k], hB = H1[k];
            if (c1) { a1A += hA * Ws3[k * P3 + cg];     a1B += hB * Ws3[k * P3 + cg]; }
            if (c2) { a2A += hA * Ws3[k * P3 + cg + 8]; a2B += hB * Ws3[k * P3 + cg + 8]; }
        }
    }
    if (kh == 1) {
        if (c1) { Obuf[lane * 17 + cg] = a1A;          Obuf[(lane + 32) * 17 + cg] = a1B; }
        if (c2) { Obuf[lane * 17 + cg + 8] = a2A;      Obuf[(lane + 32) * 17 + cg + 8] = a2B; }
    }
    __syncthreads();
    o1A = o2A = o1B = o2B = 0.f;
    if (kh == 0) {
        if (c1) { o1A = b3s[cg] + a1A + Obuf[lane * 17 + cg];
                  o1B = b3s[cg] + a1B + Obuf[(lane + 32) * 17 + cg]; }
        if (c2) { o2A = b3s[cg + 8] + a2A + Obuf[lane * 17 + cg + 8];
                  o2B = b3s[cg + 8] + a2B + Obuf[(lane + 32) * 17 + cg + 8]; }
    }
}

// ---------------- nn1 + fused LSH binning --------------------------------
__global__ __launch_bounds__(512)
void nn1_kernel(const float* __restrict__ x,
                const float* __restrict__ W1, const float* __restrict__ b1,
                const float* __restrict__ W2, const float* __restrict__ b2,
                const float* __restrict__ W3, const float* __restrict__ b3,
                const float* __restrict__ cb)
{
    extern __shared__ float sm[];
    float* Ws1 = sm;                      // 12*128
    float* Ws2 = Ws1 + 1536;              // 125*128
    float* Ws3 = Ws2 + 16000;             // 125*16
    float* b1s = Ws3 + 2000;              // 128
    float* b2s = b1s + 128;               // 128
    float* b3s = b2s + 128;               // 16
    float* H    = b3s + 16;               // 64*PH
    float* Pbuf = H + 64 * PH;            // 64*PH
    float* Obuf = Pbuf + 64 * PH;         // 64*17
    float* xinS = Obuf + 1088;            // 64*13
    float* HoutS = xinS + 832;            // 64*13
    float* cbs  = HoutS + 832;            // 300

    const int tid = threadIdx.x;
    stage_net<12, 12, 16>(W1, b1, W2, b2, W3, b3, Ws1, Ws2, Ws3, b1s, b2s, b3s, tid);
    for (int idx = tid; idx < 300; idx += 512) {
        const int k = idx / 25, c = idx % 25;
        cbs[idx] = cb[k * 100 + c];
    }
    for (int idx = tid; idx < 64 * 12; idx += 512) {
        const int r = idx / 12, c = idx % 12;
        const int row = blockIdx.x * 64 + r;
        xinS[r * 13 + c] = (row < N_NODES) ? x[row * 12 + c] : 0.f;
    }
    __syncthreads();

    const int lane = tid & 31;
    const int w16  = tid >> 5;
    const int cg   = w16 & 7;
    const int kh   = w16 >> 3;
    const int j0   = cg * 16;
    const int rowA = blockIdx.x * 64 + lane;
    const int rowB = rowA + 32;

    float o1A, o2A, o1B, o2B;
    run_mlp2<12, 12, 16>(xinS + lane * 13, xinS + (lane + 32) * 13,
                         Ws1, Ws2, Ws3, b1s, b2s, b3s,
                         H, Pbuf, Obuf, lane, j0, cg, kh, o1A, o2A, o1B, o2B);

    if (kh == 0) {
        if (rowA < N_NODES) g_h[rowA * 12 + cg] = o1A;
        if (rowB < N_NODES) g_h[rowB * 12 + cg] = o1B;
        HoutS[lane * 13 + cg] = o1A;
        HoutS[(lane + 32) * 13 + cg] = o1B;
        if (cg < 4) {
            if (rowA < N_NODES) g_h[rowA * 12 + 8 + cg] = o2A;
            if (rowB < N_NODES) g_h[rowB * 12 + 8 + cg] = o2B;
            HoutS[lane * 13 + 8 + cg] = o2A;
            HoutS[(lane + 32) * 13 + 8 + cg] = o2B;
        }
    }
    __syncthreads();

    if (tid < 64) {
        const int r2 = blockIdx.x * 64 + tid;
        if (r2 < N_NODES) {
            float hr[12];
            #pragma unroll
            for (int k = 0; k < 12; k++) hr[k] = HoutS[tid * 13 + k];
            float mul[25];
            #pragma unroll
            for (int c = 0; c < 25; c++) {
                float s = 0.f;
                #pragma unroll
                for (int k = 0; k < 12; k++) s += hr[k] * cbs[k * 25 + c];
                mul[c] = s;
            }
            float best = -3.4e38f; int bi = 0;
            #pragma unroll
            for (int c = 0; c < 50; c++) {
                const float v = (c < 25) ? mul[c] : -mul[c - 25];
                if (v > best) { best = v; bi = c; }   // first-max: jnp.argmax
            }
            g_bin[r2] = bi;
        }
    }
}

// ---------------- nn2 (g_hf -> cand_ids) + passthrough copies -------------
__global__ __launch_bounds__(512)
void nn2_kernel(const float* __restrict__ W1, const float* __restrict__ b1,
                const float* __restrict__ W2, const float* __restrict__ b2,
                const float* __restrict__ W3, const float* __restrict__ b3,
                float* __restrict__ cand_ids,
                const float* __restrict__ ygen_id, float* __restrict__ out_yid,
                const float* __restrict__ ygen,    float* __restrict__ out_yg)
{
    extern __shared__ float sm[];
    float* Ws1 = sm;                      // 32*128
    float* Ws2 = Ws1 + 4096;              // 125*128
    float* Ws3 = Ws2 + 16000;             // 125*8
    float* b1s = Ws3 + 1000;              // 128
    float* b2s = b1s + 128;
    float* b3s = b2s + 128;               // 16
    float* H    = b3s + 16;               // 64*PH
    float* Pbuf = H + 64 * PH;            // 64*PH
    float* Obuf = Pbuf + 64 * PH;         // 64*17
    float* xinS = Obuf + 1088;            // 64*33

    const int tid = threadIdx.x;
    const int gt  = blockIdx.x * 512 + tid;
    if (gt < 30000) { out_yid[gt] = ygen_id[gt]; out_yg[gt] = ygen[gt]; }

    stage_net<32, 6, 8>(W1, b1, W2, b2, W3, b3, Ws1, Ws2, Ws3, b1s, b2s, b3s, tid);
    for (int idx = tid; idx < 64 * 32; idx += 512) {
        const int r = idx >> 5, c = idx & 31;
        const int row = blockIdx.x * 64 + r;
        xinS[r * 33 + c] = (row < N_NODES) ? g_hf[row * 32 + c] : 0.f;
    }
    __syncthreads();

    const int lane = tid & 31;
    const int w16  = tid >> 5;
    const int cg   = w16 & 7;
    const int kh   = w16 >> 3;
    const int j0   = cg * 16;
    const int rowA = blockIdx.x * 64 + lane;
    const int rowB = rowA + 32;

    float o1A, o2A, o1B, o2B;
    run_mlp2<32, 6, 8>(xinS + lane * 33, xinS + (lane + 32) * 33,
                       Ws1, Ws2, Ws3, b1s, b2s, b3s,
                       H, Pbuf, Obuf, lane, j0, cg, kh, o1A, o2A, o1B, o2B);

    if (kh == 0 && cg < 6) {
        if (rowA < N_NODES) cand_ids[rowA * 6 + cg] = o1A;
        if (rowB < N_NODES) cand_ids[rowB * 6 + cg] = o1B;
    }
}

// ---------------- nn3 ([g_hf, cand_ids] -> cand_p4) -----------------------
__global__ __launch_bounds__(512)
void nn3_kernel(const float* __restrict__ W1, const float* __restrict__ b1,
                const float* __restrict__ W2, const float* __restrict__ b2,
                const float* __restrict__ W3, const float* __restrict__ b3,
                const float* __restrict__ cand_ids, float* __restrict__ cand_p4)
{
    extern __shared__ float sm[];
    float* Ws1 = sm;                      // 38*128
    float* Ws2 = Ws1 + 4864;              // 125*128
    float* Ws3 = Ws2 + 16000;             // 125*8
    float* b1s = Ws3 + 1000;              // 128
    float* b2s = b1s + 128;
    float* b3s = b2s + 128;               // 16
    float* H    = b3s + 16;               // 64*PH
    float* Pbuf = H + 64 * PH;            // 64*PH
    float* Obuf = Pbuf + 64 * PH;         // 64*17
    float* xinS = Obuf + 1088;            // 64*39

    const int tid = threadIdx.x;
    stage_net<38, 6, 8>(W1, b1, W2, b2, W3, b3, Ws1, Ws2, Ws3, b1s, b2s, b3s, tid);
    for (int idx = tid; idx < 64 * 32; idx += 512) {
        const int r = idx >> 5, c = idx & 31;
        const int row = blockIdx.x * 64 + r;
        xinS[r * 39 + c] = (row < N_NODES) ? g_hf[row * 32 + c] : 0.f;
    }
    for (int idx = tid; idx < 64 * 6; idx += 512) {
        const int r = idx / 6, c = idx % 6;
        const int row = blockIdx.x * 64 + r;
        xinS[r * 39 + 32 + c] = (row < N_NODES) ? cand_ids[row * 6 + c] : 0.f;
    }
    __syncthreads();

    const int lane = tid & 31;
    const int w16  = tid >> 5;
    const int cg   = w16 & 7;
    const int kh   = w16 >> 3;
    const int j0   = cg * 16;
    const int rowA = blockIdx.x * 64 + lane;
    const int rowB = rowA + 32;

    float o1A, o2A, o1B, o2B;
    run_mlp2<38, 6, 8>(xinS + lane * 39, xinS + (lane + 32) * 39,
                       Ws1, Ws2, Ws3, b1s, b2s, b3s,
                       H, Pbuf, Obuf, lane, j0, cg, kh, o1A, o2A, o1B, o2B);

    if (kh == 0 && cg < 6) {
        if (rowA < N_NODES) cand_p4[rowA * 6 + cg] = o1A;
        if (rowB < N_NODES) cand_p4[rowB * 6 + cg] = o1B;
    }
}

// ---------------- stable counting-sort (verbatim) --------------------------
__global__ __launch_bounds__(256, 1) void sort_kernel()
{
    __shared__ int cB[8], cL[8];
    const int b = blockIdx.x;
    const int w = threadIdx.x >> 5, lane = threadIdx.x & 31;
    const int beg = w * 625, end = beg + 625;

    int nB = 0, nL = 0;
    for (int i0 = beg; i0 < end; i0 += 32) {
        const int i = i0 + lane;
        const bool inr = i < end;
        const int bv = inr ? g_bin[i] : 0x7fffffff;
        nB += __popc(__ballot_sync(0xffffffffu, inr && bv == b));
        nL += __popc(__ballot_sync(0xffffffffu, inr && bv <  b));
    }
    if (lane == 0) { cB[w] = nB; cL[w] = nL; }
    __syncthreads();

    int off = 0;
    #pragma unroll
    for (int q = 0; q < 8; q++) off += cL[q];
    for (int q = 0; q < w; q++) off += cB[q];

    for (int i0 = beg; i0 < end; i0 += 32) {
        const int i = i0 + lane;
        const bool inr = i < end;
        const int bv = inr ? g_bin[i] : 0x7fffffff;
        const bool p = inr && bv == b;
        const unsigned m = __ballot_sync(0xffffffffu, p);
        if (p) g_sorted[off + __popc(m & ((1u << lane) - 1u))] = i;
        off += __popc(m);
    }
}

// ---------------- similarity + top-16 (grid = 100: 2 blocks per bin) -------
__global__ __launch_bounds__(512, 2)
void bin_sim_kernel()
{
    __shared__ float P[1300];     // 100 x 13
    __shared__ float D[50 * 101]; // this block's 50 rows
    __shared__ int   sids[100];

    const int tid = threadIdx.x;
    const int b    = blockIdx.x >> 1;
    const int half = blockIdx.x & 1;
    const int r0   = half * 50;

    if (tid < 100) sids[tid] = g_sorted[b * 100 + tid];
    __syncthreads();
    for (int idx = tid; idx < 1200; idx += 512) {
        const int i = idx / 12, k = idx % 12;
        P[i * 13 + k] = g_h[sids[i] * 12 + k];
    }
    __syncthreads();

    // rows r0..r0+49, all j. dot k-order identical to the symmetric variant,
    // and a*b == b*a bitwise -> values match the reference triangle exactly.
    for (int p = tid; p < 5000; p += 512) {
        const int lr = p / 100;        // local row 0..49
        const int i  = r0 + lr;
        const int j  = p % 100;
        float s = 0.f;
        #pragma unroll
        for (int k = 0; k < 12; k++) s += P[i * 13 + k] * P[j * 13 + k];
        D[lr * 101 + j] = 1.f / (1.f + __expf(-s));
    }
    __syncthreads();

    // top-16: streaming insertion (stable: strict >, earlier index wins ties)
    if (tid < 50) {
        const float* Drow = D + tid * 101;
        const int r = r0 + tid;
        float tv[16]; int tj[16];
        #pragma unroll
        for (int s = 0; s < 16; s++) { tv[s] = -1.f; tj[s] = 0; }
        for (int j = 0; j < 100; j++) {
            const float v = Drow[j];
            if (v > tv[15]) {
                #pragma unroll
                for (int s = 15; s >= 1; s--) {
                    const bool up = (v > tv[s - 1]);
                    const bool here = !up && (v > tv[s]);
                    tv[s] = up ? tv[s - 1] : (here ? v : tv[s]);
                    tj[s] = up ? tj[s - 1] : (here ? j : tj[s]);
                }
                if (v > tv[0]) { tv[0] = v; tj[0] = j; }
            }
        }
        #pragma unroll
        for (int s = 0; s < 16; s++) {
            g_Ew[b * 1600 + r * 16 + s] = tv[s];
            g_Ed[b * 1600 + r * 16 + s] = tj[s];
        }
    }
}

// ---------------- per-bin conv: CSR, GCNConv, GraphConv --------------------
__global__ __launch_bounds__(512, 1)
void bin_conv_kernel(const float* __restrict__ gcnW, const float* __restrict__ gcnb,
                     const float* __restrict__ Wrel, const float* __restrict__ brel,
                     const float* __restrict__ Wroot)
{
    extern __shared__ float sm[];
    float* P    = sm;                   // 100 x 13
    float* HW   = P + 1300;             // 100 x 33
    float* GC   = HW + 3300;
    float* AGG  = GC + 3300;
    float* Ew   = AGG + 3300;           // 1600
    float* coef = Ew + 1600;            // 1600
    float* degf = coef + 1600;          // 100
    float* gws  = degf + 100;           // 384
    float* gbs  = gws + 384;            // 32
    float* wrs  = gbs + 32;             // 1024
    float* wts  = wrs + 1024;           // 1024
    float* brs  = wts + 1024;           // 32
    int* sids  = (int*)(brs + 32);      // 100
    int* Ed    = sids + 100;            // 1600
    int* roff  = Ed + 1600;             // 128
    int* cnt   = roff + 128;            // 100
    int* rlist = cnt + 100;             // 1600

    const int tid = threadIdx.x;
    const int b = blockIdx.x;

    if (tid < 100) sids[tid] = g_sorted[b * 100 + tid];
    for (int idx = tid; idx < 384; idx += 512) gws[idx] = gcnW[idx];
    for (int idx = tid; idx < 1024; idx += 512) { wrs[idx] = Wrel[idx]; wts[idx] = Wroot[idx]; }
    if (tid < 32) { gbs[tid] = gcnb[tid]; brs[tid] = brel[tid]; }
    if (tid < 128) roff[tid] = 0;
    if (tid < 100) cnt[tid] = 0;
    for (int e = tid; e < 1600; e += 512) {
        Ew[e] = g_Ew[b * 1600 + e];
        Ed[e] = g_Ed[b * 1600 + e];
    }
    __syncthreads();
    for (int idx = tid; idx < 1200; idx += 512) {
        const int i = idx / 12, k = idx % 12;
        P[i * 13 + k] = g_h[sids[i] * 12 + k];
    }

    // reverse CSR
    for (int e = tid; e < 1600; e += 512) atomicAdd(&roff[Ed[e] + 1], 1);
    __syncthreads();
    for (int d = 1; d < 128; d <<= 1) {
        int v = 0;
        if (tid < 101 && tid >= d) v = roff[tid - d];
        __syncthreads();
        if (tid < 101) roff[tid] += v;
        __syncthreads();
    }
    for (int e = tid; e < 1600; e += 512) {
        const int d = Ed[e];
        const int slot = atomicAdd(&cnt[d], 1);
        rlist[roff[d] + slot] = e;
    }
    __syncthreads();

    if (tid < 100) {
        float dg = 1.f;
        const int q1 = roff[tid + 1];
        for (int q = roff[tid]; q < q1; q++) dg += Ew[rlist[q]];
        degf[tid] = 1.f / sqrtf(dg);
    }
    __syncthreads();

    for (int idx = tid; idx < 1300; idx += 512) P[idx] = lrelu(P[idx]);
    for (int e = tid; e < 1600; e += 512) coef[e] = Ew[e] * degf[e >> 4];
    __syncthreads();

    const int f  = tid & 31;
    const int c0 = tid >> 5;

    for (int c = c0; c < 100; c += 16) {
        float a = 0.f;
        #pragma unroll
        for (int k = 0; k < 12; k++) a += P[c * 13 + k] * gws[k * 32 + f];
        HW[c * 33 + f] = a;
    }
    __syncthreads();

    for (int c = c0; c < 100; c += 16) {
        float a = 0.f;
        const int q1 = roff[c + 1];
        for (int q = roff[c]; q < q1; q++) {
            const int e = rlist[q];
            a += coef[e] * HW[(e >> 4) * 33 + f];
        }
        const float dc = degf[c];
        GC[c * 33 + f] = gbs[f] + dc * a + dc * dc * HW[c * 33 + f];
    }
    __syncthreads();

    for (int c = c0; c < 100; c += 16) {
        float a = 0.f;
        const int q1 = roff[c + 1];
        for (int q = roff[c]; q < q1; q++) {
            const int e = rlist[q];
            a += Ew[e] * GC[(e >> 4) * 33 + f];
        }
        AGG[c * 33 + f] = a;
    }
    __syncthreads();

    for (int c = c0; c < 100; c += 16) {
        float a = brs[f];
        #pragma unroll
        for (int k = 0; k < 32; k++) a += AGG[c * 33 + k] * wrs[k * 32 + f] + GC[c * 33 + k] * wts[k * 32 + f];
        g_hf[sids[c] * 32 + f] = lrelu(a);
    }
}

// ---------------- host launcher ------------------------------------------
static size_t nn1_smem() {
    return (size_t)(1536 + 16000 + 2000 + 272 + 64 * PH * 2 + 1088 + 832 + 832 + 300) * 4;
}
static size_t nn2_smem() {
    return (size_t)(4096 + 16000 + 1000 + 272 + 64 * PH * 2 + 1088 + 64 * 33) * 4;
}
static size_t nn3_smem() {
    return (size_t)(4864 + 16000 + 1000 + 272 + 64 * PH * 2 + 1088 + 64 * 39) * 4;
}
static size_t binc_smem() {
    size_t fl = 1300 + 3 * 3300 + 1600 + 1600 + 100 + 384 + 32 + 1024 + 1024 + 32;
    size_t in = 100 + 1600 + 128 + 100 + 1600;
    return (fl + in) * 4;
}

extern "C" void kernel_launch(void* const* d_in, const int* in_sizes, int n_in,
                              void* d_out, int out_size)
{
    const float* x       = (const float*)d_in[0];
    const float* ygen_id = (const float*)d_in[1];
    const float* ygen    = (const float*)d_in[2];
    const float* cb      = (const float*)d_in[3];
    const float* nn1_W1 = (const float*)d_in[4];
    const float* nn1_b1 = (const float*)d_in[5];
    const float* nn1_W2 = (const float*)d_in[6];
    const float* nn1_b2 = (const float*)d_in[7];
    const float* nn1_W3 = (const float*)d_in[8];
    const float* nn1_b3 = (const float*)d_in[9];
    const float* gcn_W  = (const float*)d_in[10];
    const float* gcn_b  = (const float*)d_in[11];
    const float* gc_Wrel  = (const float*)d_in[12];
    const float* gc_brel  = (const float*)d_in[13];
    const float* gc_Wroot = (const float*)d_in[14];
    const float* nn2_W1 = (const float*)d_in[15];
    const float* nn2_b1 = (const float*)d_in[16];
    const float* nn2_W2 = (const float*)d_in[17];
    const float* nn2_b2 = (const float*)d_in[18];
    const float* nn2_W3 = (const float*)d_in[19];
    const float* nn2_b3 = (const float*)d_in[20];
    const float* nn3_W1 = (const float*)d_in[21];
    const float* nn3_b1 = (const float*)d_in[22];
    const float* nn3_W2 = (const float*)d_in[23];
    const float* nn3_b2 = (const float*)d_in[24];
    const float* nn3_W3 = (const float*)d_in[25];
    const float* nn3_b3 = (const float*)d_in[26];

    float* out = (float*)d_out;

    cudaFuncSetAttribute(nn1_kernel, cudaFuncAttributeMaxDynamicSharedMemorySize, (int)nn1_smem());
    cudaFuncSetAttribute(nn2_kernel, cudaFuncAttributeMaxDynamicSharedMemorySize, (int)nn2_smem());
    cudaFuncSetAttribute(nn3_kernel, cudaFuncAttributeMaxDynamicSharedMemorySize, (int)nn3_smem());
    cudaFuncSetAttribute(bin_conv_kernel, cudaFuncAttributeMaxDynamicSharedMemorySize, (int)binc_smem());

    const int grid = (N_NODES + 63) / 64;   // 79

    nn1_kernel<<<grid, 512, nn1_smem()>>>(x, nn1_W1, nn1_b1, nn1_W2, nn1_b2, nn1_W3, nn1_b3, cb);
    sort_kernel<<<NBINS, 256>>>();
    bin_sim_kernel<<<2 * NBINS, 512>>>();
    bin_conv_kernel<<<NBINS, 512, binc_smem()>>>(gcn_W, gcn_b, gc_Wrel, gc_brel, gc_Wroot);
    nn2_kernel<<<grid, 512, nn2_smem()>>>(nn2_W1, nn2_b1, nn2_W2, nn2_b2, nn2_W3, nn2_b3,
                                          out, ygen_id, out + 60000, ygen, out + 90000);
    nn3_kernel<<<grid, 512, nn3_smem()>>>(nn3_W1, nn3_b1, nn3_W2, nn3_b2, nn3_W3, nn3_b3,
                                          out, out + 30000);
}

// round 15
// speedup vs baseline: 1.2478x; 1.0687x over previous
#include <cuda_runtime.h>
#include <math.h>

#define N_NODES 5000
#define NBINS 50
#define KNN 16
#define SLOPE 0.01f
#define PH 129   // hidden-buffer pitch (129 mod 32 = 1 -> conflict-free)

// ---------------- device scratch ----------------
__device__ float g_h[N_NODES * 12];     // nn1 output (pre-leaky)
__device__ int   g_bin[N_NODES];
__device__ int   g_sorted[N_NODES];     // stable argsort of g_bin
__device__ float g_hf[N_NODES * 32];    // post-conv, post-leaky features

__device__ __forceinline__ float lrelu(float v) { return v > 0.f ? v : SLOPE * v; }

__device__ __forceinline__ unsigned long long pack2(float a, float b) {
    unsigned long long r;
    asm("mov.b64 %0, {%1, %2};" : "=l"(r) : "r"(__float_as_uint(a)), "r"(__float_as_uint(b)));
    return r;
}
__device__ __forceinline__ void unpack2(unsigned long long p, float& a, float& b) {
    unsigned int x, y;
    asm("mov.b64 {%0, %1}, %2;" : "=r"(x), "=r"(y) : "l"(p));
    a = __uint_as_float(x); b = __uint_as_float(y);
}
__device__ __forceinline__ unsigned long long ffma2(unsigned long long a, unsigned long long b, unsigned long long c) {
    unsigned long long d;
    asm("fma.rn.f32x2 %0, %1, %2, %3;" : "=l"(d) : "l"(a), "l"(b), "l"(c));
    return d;
}

// ---------------- MLP machinery -------------------------------------------
// 512 threads, 64 rows/block (2 rows per lane: lane and lane+32), grid = 79.
// warp w16 = tid>>5: cg = w16 & 7 (16-col slice, j0 = cg*16), kh = w16>>3
// (K-half). Weights staged in smem. K-split partner partials are exchanged
// THROUGH H (kh=1 stores raw partial; bar; kh=0 combines bias+partial+own).

template <int IN, int OUT, int P3>
__device__ __forceinline__ void stage_net(
    const float* __restrict__ W1, const float* __restrict__ b1,
    const float* __restrict__ W2, const float* __restrict__ b2,
    const float* __restrict__ W3, const float* __restrict__ b3,
    float* Ws1, float* Ws2, float* Ws3, float* b1s, float* b2s, float* b3s, int tid)
{
    for (int idx = tid; idx < IN * 128; idx += 512) {
        const int k = idx >> 7, j = idx & 127;
        Ws1[idx] = (j < 125) ? W1[k * 125 + j] : 0.f;
    }
    for (int idx = tid; idx < 125 * 128; idx += 512) {
        const int k = idx >> 7, j = idx & 127;
        Ws2[idx] = (j < 125) ? W2[k * 125 + j] : 0.f;
    }
    for (int idx = tid; idx < 125 * P3; idx += 512) {
        const int k = idx / P3, o = idx % P3;
        Ws3[idx] = (o < OUT) ? W3[k * OUT + o] : 0.f;
    }
    if (tid < 128) {
        b1s[tid] = (tid < 125) ? b1[tid] : 0.f;
        b2s[tid] = (tid < 125) ? b2[tid] : 0.f;
    } else if (tid < 144) {
        const int o = tid - 128;
        b3s[o] = (o < OUT) ? b3[o] : 0.f;
    }
}

// two-row dense: acc[8] per row, weights loaded once per k
template <int K0, int K1>
__device__ __forceinline__ void dense_range2(const float* __restrict__ Ws,
                                             const float* __restrict__ x0,
                                             const float* __restrict__ x1,
                                             int j0,
                                             unsigned long long accA[8],
                                             unsigned long long accB[8])
{
    #pragma unroll 5
    for (int k = K0; k < K1; k++) {
        const float va = x0[k], vb = x1[k];
        const unsigned long long xa = pack2(va, va);
        const unsigned long long xb = pack2(vb, vb);
        const ulonglong2* wp = (const ulonglong2*)(Ws + k * 128 + j0);
        const ulonglong2 wa = wp[0], wb = wp[1], wc = wp[2], wd = wp[3];
        accA[0] = ffma2(xa, wa.x, accA[0]); accA[1] = ffma2(xa, wa.y, accA[1]);
        accA[2] = ffma2(xa, wb.x, accA[2]); accA[3] = ffma2(xa, wb.y, accA[3]);
        accA[4] = ffma2(xa, wc.x, accA[4]); accA[5] = ffma2(xa, wc.y, accA[5]);
        accA[6] = ffma2(xa, wd.x, accA[6]); accA[7] = ffma2(xa, wd.y, accA[7]);
        accB[0] = ffma2(xb, wa.x, accB[0]); accB[1] = ffma2(xb, wa.y, accB[1]);
        accB[2] = ffma2(xb, wb.x, accB[2]); accB[3] = ffma2(xb, wb.y, accB[3]);
        accB[4] = ffma2(xb, wc.x, accB[4]); accB[5] = ffma2(xb, wc.y, accB[5]);
        accB[6] = ffma2(xb, wd.x, accB[6]); accB[7] = ffma2(xb, wd.y, accB[7]);
    }
}

__device__ __forceinline__ void zero8(unsigned long long a[8]) {
    #pragma unroll
    for (int m = 0; m < 8; m++) a[m] = pack2(0.f, 0.f);
}
__device__ __forceinline__ void store_partial(unsigned long long acc[8], float* dst) {
    #pragma unroll
    for (int m = 0; m < 8; m++) {
        float a, b; unpack2(acc[m], a, b);
        dst[2 * m] = a; dst[2 * m + 1] = b;
    }
}
// Pb may alias Hd (per-element read then write is safe)
__device__ __forceinline__ void combine_act(unsigned long long acc[8], const float* __restrict__ bS,
                                            const float* Pb, float* Hd, int j0)
{
    #pragma unroll
    for (int m = 0; m < 8; m++) {
        float a, b; unpack2(acc[m], a, b);
        const int j = j0 + 2 * m;
        const float b0 = (j < 125) ? bS[j] : 0.f;
        const float b1 = (j + 1 < 125) ? bS[j + 1] : 0.f;
        const float p0 = Pb[j], p1 = Pb[j + 1];
        Hd[j]     = lrelu(b0 + a + p0);
        Hd[j + 1] = lrelu(b1 + b + p1);
    }
}

// 3-layer net, K-split + 2 rows/lane, partials exchanged through H.
template <int IN, int OUT, int P3>
__device__ __forceinline__ void run_mlp2h(
    const float* __restrict__ x0, const float* __restrict__ x1,
    const float* Ws1, const float* Ws2, const float* Ws3,
    const float* b1s, const float* b2s, const float* b3s,
    float* H, float* Obuf,
    int lane, int j0, int cg, int kh,
    float& o1A, float& o2A, float& o1B, float& o2B)
{
    unsigned long long accA[8], accB[8];
    float* H0 = H + lane * PH;
    float* H1 = H + (lane + 32) * PH;

    // ---- layer 1 (H not yet live) ----
    zero8(accA); zero8(accB);
    if (kh == 0) dense_range2<0, IN / 2>(Ws1, x0, x1, j0, accA, accB);
    else         dense_range2<IN / 2, IN>(Ws1, x0, x1, j0, accA, accB);
    if (kh == 1) { store_partial(accA, H0 + j0); store_partial(accB, H1 + j0); }
    __syncthreads();
    if (kh == 0) { combine_act(accA, b1s, H0, H0, j0); combine_act(accB, b1s, H1, H1, j0); }
    __syncthreads();

    // ---- layer 2 (K=125) ----
    zero8(accA); zero8(accB);
    if (kh == 0) dense_range2<0, 63>(Ws2, H0, H1, j0, accA, accB);
    else         dense_range2<63, 125>(Ws2, H0, H1, j0, accA, accB);
    __syncthreads();                     // all H reads complete before overwrite
    if (kh == 1) { store_partial(accA, H0 + j0); store_partial(accB, H1 + j0); }
    __syncthreads();
    if (kh == 0) { combine_act(accA, b2s, H0, H0, j0); combine_act(accB, b2s, H1, H1, j0); }
    __syncthreads();

    // ---- layer 3 ----
    const bool c1 = (cg < OUT);
    const bool c2 = (OUT > 8) && (cg + 8 < OUT);
    float a1A = 0.f, a2A = 0.f, a1B = 0.f, a2B = 0.f;
    if (kh == 0) {
        #pragma unroll 7
        for (int k = 0; k < 63; k++) {
            const float hA = H0[k], hB = H1[k];
            if (c1) { a1A += hA * Ws3[k * P3 + cg];     a1B += hB * Ws3[k * P3 + cg]; }
            if (c2) { a2A += hA * Ws3[k * P3 + cg + 8]; a2B += hB * Ws3[k * P3 + cg + 8]; }
        }
    } else {
        #pragma unroll 7
        for (int k = 63; k < 125; k++) {
            const float hA = H0[k], hB = H1[k];
            if (c1) { a1A += hA * Ws3[k * P3 + cg];     a1B += hB * Ws3[k * P3 + cg]; }
            if (c2) { a2A += hA * Ws3[k * P3 + cg + 8]; a2B += hB * Ws3[k * P3 + cg + 8]; }
        }
    }
    if (kh == 1) {
        if (c1) { Obuf[lane * 17 + cg] = a1A;          Obuf[(lane + 32) * 17 + cg] = a1B; }
        if (c2) { Obuf[lane * 17 + cg + 8] = a2A;      Obuf[(lane + 32) * 17 + cg + 8] = a2B; }
    }
    __syncthreads();
    o1A = o2A = o1B = o2B = 0.f;
    if (kh == 0) {
        if (c1) { o1A = b3s[cg] + a1A + Obuf[lane * 17 + cg];
                  o1B = b3s[cg] + a1B + Obuf[(lane + 32) * 17 + cg]; }
        if (c2) { o2A = b3s[cg + 8] + a2A + Obuf[lane * 17 + cg + 8];
                  o2B = b3s[cg + 8] + a2B + Obuf[(lane + 32) * 17 + cg + 8]; }
    }
}

// ---------------- nn1 + fused LSH binning --------------------------------
__global__ __launch_bounds__(512)
void nn1_kernel(const float* __restrict__ x,
                const float* __restrict__ W1, const float* __restrict__ b1,
                const float* __restrict__ W2, const float* __restrict__ b2,
                const float* __restrict__ W3, const float* __restrict__ b3,
                const float* __restrict__ cb)
{
    extern __shared__ float sm[];
    float* Ws1 = sm;                      // 12*128 = 1536
    float* Ws2 = Ws1 + 1536;              // 16000
    float* Ws3 = Ws2 + 16000;             // 125*16 = 2000
    float* b1s = Ws3 + 2000;              // 128
    float* b2s = b1s + 128;               // 128
    float* b3s = b2s + 128;               // 16
    float* H    = b3s + 16;               // 64*PH = 8256
    float* Obuf = H + 64 * PH;            // 1088
    float* xinS = Obuf + 1088;            // 64*13 = 832
    float* HoutS = xinS + 832;            // 832
    float* cbs  = HoutS + 832;            // 300

    const int tid = threadIdx.x;
    stage_net<12, 12, 16>(W1, b1, W2, b2, W3, b3, Ws1, Ws2, Ws3, b1s, b2s, b3s, tid);
    for (int idx = tid; idx < 300; idx += 512) {
        const int k = idx / 25, c = idx % 25;
        cbs[idx] = cb[k * 100 + c];
    }
    for (int idx = tid; idx < 64 * 12; idx += 512) {
        const int r = idx / 12, c = idx % 12;
        const int row = blockIdx.x * 64 + r;
        xinS[r * 13 + c] = (row < N_NODES) ? x[row * 12 + c] : 0.f;
    }
    __syncthreads();

    const int lane = tid & 31;
    const int w16  = tid >> 5;
    const int cg   = w16 & 7;
    const int kh   = w16 >> 3;
    const int j0   = cg * 16;
    const int rowA = blockIdx.x * 64 + lane;
    const int rowB = rowA + 32;

    float o1A, o2A, o1B, o2B;
    run_mlp2h<12, 12, 16>(xinS + lane * 13, xinS + (lane + 32) * 13,
                          Ws1, Ws2, Ws3, b1s, b2s, b3s,
                          H, Obuf, lane, j0, cg, kh, o1A, o2A, o1B, o2B);

    if (kh == 0) {
        if (rowA < N_NODES) g_h[rowA * 12 + cg] = o1A;
        if (rowB < N_NODES) g_h[rowB * 12 + cg] = o1B;
        HoutS[lane * 13 + cg] = o1A;
        HoutS[(lane + 32) * 13 + cg] = o1B;
        if (cg < 4) {
            if (rowA < N_NODES) g_h[rowA * 12 + 8 + cg] = o2A;
            if (rowB < N_NODES) g_h[rowB * 12 + 8 + cg] = o2B;
            HoutS[lane * 13 + 8 + cg] = o2A;
            HoutS[(lane + 32) * 13 + 8 + cg] = o2B;
        }
    }
    __syncthreads();

    if (tid < 64) {
        const int r2 = blockIdx.x * 64 + tid;
        if (r2 < N_NODES) {
            float hr[12];
            #pragma unroll
            for (int k = 0; k < 12; k++) hr[k] = HoutS[tid * 13 + k];
            float mul[25];
            #pragma unroll
            for (int c = 0; c < 25; c++) {
                float s = 0.f;
                #pragma unroll
                for (int k = 0; k < 12; k++) s += hr[k] * cbs[k * 25 + c];
                mul[c] = s;
            }
            float best = -3.4e38f; int bi = 0;
            #pragma unroll
            for (int c = 0; c < 50; c++) {
                const float v = (c < 25) ? mul[c] : -mul[c - 25];
                if (v > best) { best = v; bi = c; }   // first-max: jnp.argmax
            }
            g_bin[r2] = bi;
        }
    }
}

// ---------------- fused nn2 + nn3 (+ passthrough copies) ------------------
__global__ __launch_bounds__(512)
void nn23_kernel(const float* __restrict__ A_W1, const float* __restrict__ A_b1,
                 const float* __restrict__ A_W2, const float* __restrict__ A_b2,
                 const float* __restrict__ A_W3, const float* __restrict__ A_b3,
                 const float* __restrict__ B_W1, const float* __restrict__ B_b1,
                 const float* __restrict__ B_W2, const float* __restrict__ B_b2,
                 const float* __restrict__ B_W3, const float* __restrict__ B_b3,
                 float* __restrict__ cand_ids, float* __restrict__ cand_p4,
                 const float* __restrict__ ygen_id, float* __restrict__ out_yid,
                 const float* __restrict__ ygen,    float* __restrict__ out_yg)
{
    extern __shared__ float sm[];
    float* AWs1 = sm;                     // 32*128 = 4096
    float* AWs2 = AWs1 + 4096;            // 16000
    float* AWs3 = AWs2 + 16000;           // 125*8 = 1000
    float* Ab1  = AWs3 + 1000;            // 128
    float* Ab2  = Ab1 + 128;              // 128
    float* Ab3  = Ab2 + 128;              // 16
    float* BWs1 = Ab3 + 16;               // 38*128 = 4864
    float* BWs2 = BWs1 + 4864;            // 16000
    float* BWs3 = BWs2 + 16000;           // 1000
    float* Bb1  = BWs3 + 1000;            // 128
    float* Bb2  = Bb1 + 128;              // 128
    float* Bb3  = Bb2 + 128;              // 16
    float* H    = Bb3 + 16;               // 64*PH = 8256
    float* Obuf = H + 64 * PH;            // 1088
    float* xinS = Obuf + 1088;            // 64*39 = 2496

    const int tid = threadIdx.x;
    const int gt  = blockIdx.x * 512 + tid;
    if (gt < 30000) { out_yid[gt] = ygen_id[gt]; out_yg[gt] = ygen[gt]; }

    stage_net<32, 6, 8>(A_W1, A_b1, A_W2, A_b2, A_W3, A_b3, AWs1, AWs2, AWs3, Ab1, Ab2, Ab3, tid);
    stage_net<38, 6, 8>(B_W1, B_b1, B_W2, B_b2, B_W3, B_b3, BWs1, BWs2, BWs3, Bb1, Bb2, Bb3, tid);
    for (int idx = tid; idx < 64 * 32; idx += 512) {
        const int r = idx >> 5, c = idx & 31;
        const int row = blockIdx.x * 64 + r;
        xinS[r * 39 + c] = (row < N_NODES) ? g_hf[row * 32 + c] : 0.f;
    }
    __syncthreads();

    const int lane = tid & 31;
    const int w16  = tid >> 5;
    const int cg   = w16 & 7;
    const int kh   = w16 >> 3;
    const int j0   = cg * 16;
    const int rowA = blockIdx.x * 64 + lane;
    const int rowB = rowA + 32;

    float o1A, o2A, o1B, o2B;
    run_mlp2h<32, 6, 8>(xinS + lane * 39, xinS + (lane + 32) * 39,
                        AWs1, AWs2, AWs3, Ab1, Ab2, Ab3,
                        H, Obuf, lane, j0, cg, kh, o1A, o2A, o1B, o2B);

    if (kh == 0 && cg < 6) {
        if (rowA < N_NODES) cand_ids[rowA * 6 + cg] = o1A;
        if (rowB < N_NODES) cand_ids[rowB * 6 + cg] = o1B;
        xinS[lane * 39 + 32 + cg] = o1A;
        xinS[(lane + 32) * 39 + 32 + cg] = o1B;
    }
    __syncthreads();

    run_mlp2h<38, 6, 8>(xinS + lane * 39, xinS + (lane + 32) * 39,
                        BWs1, BWs2, BWs3, Bb1, Bb2, Bb3,
                        H, Obuf, lane, j0, cg, kh, o1A, o2A, o1B, o2B);

    if (kh == 0 && cg < 6) {
        if (rowA < N_NODES) cand_p4[rowA * 6 + cg] = o1A;
        if (rowB < N_NODES) cand_p4[rowB * 6 + cg] = o1B;
    }
}

// ---------------- stable counting-sort (verbatim) --------------------------
__global__ __launch_bounds__(256, 1) void sort_kernel()
{
    __shared__ int cB[8], cL[8];
    const int b = blockIdx.x;
    const int w = threadIdx.x >> 5, lane = threadIdx.x & 31;
    const int beg = w * 625, end = beg + 625;

    int nB = 0, nL = 0;
    for (int i0 = beg; i0 < end; i0 += 32) {
        const int i = i0 + lane;
        const bool inr = i < end;
        const int bv = inr ? g_bin[i] : 0x7fffffff;
        nB += __popc(__ballot_sync(0xffffffffu, inr && bv == b));
        nL += __popc(__ballot_sync(0xffffffffu, inr && bv <  b));
    }
    if (lane == 0) { cB[w] = nB; cL[w] = nL; }
    __syncthreads();

    int off = 0;
    #pragma unroll
    for (int q = 0; q < 8; q++) off += cL[q];
    for (int q = 0; q < w; q++) off += cB[q];

    for (int i0 = beg; i0 < end; i0 += 32) {
        const int i = i0 + lane;
        const bool inr = i < end;
        const int bv = inr ? g_bin[i] : 0x7fffffff;
        const bool p = inr && bv == b;
        const unsigned m = __ballot_sync(0xffffffffu, p);
        if (p) g_sorted[off + __popc(m & ((1u << lane) - 1u))] = i;
        off += __popc(m);
    }
}

// ---------------- per-chunk graph kernel (R12 monolith, verbatim) ---------
__global__ __launch_bounds__(512, 1)
void bin_kernel(const float* __restrict__ gcnW, const float* __restrict__ gcnb,
                const float* __restrict__ Wrel, const float* __restrict__ brel,
                const float* __restrict__ Wroot)
{
    extern __shared__ float sm[];
    float* P    = sm;                   // 100 x 13
    float* D    = P + 1300;             // 100 x 101
    float* HW   = D + 10100;            // 100 x 33
    float* GC   = HW + 3300;
    float* AGG  = GC + 3300;
    float* Ew   = AGG + 3300;           // 1600
    float* coef = Ew + 1600;            // 1600
    float* degf = coef + 1600;          // 100
    float* gws  = degf + 100;           // 384
    float* gbs  = gws + 384;            // 32
    float* wrs  = gbs + 32;             // 1024
    float* wts  = wrs + 1024;           // 1024
    float* brs  = wts + 1024;           // 32
    int* sids  = (int*)(brs + 32);      // 100
    int* Ed    = sids + 100;            // 1600
    int* roff  = Ed + 1600;             // 128
    int* cnt   = roff + 128;            // 100
    int* rlist = cnt + 100;             // 1600

    const int tid = threadIdx.x;
    const int b = blockIdx.x;

    if (tid < 100) sids[tid] = g_sorted[b * 100 + tid];
    for (int idx = tid; idx < 384; idx += 512) gws[idx] = gcnW[idx];
    for (int idx = tid; idx < 1024; idx += 512) { wrs[idx] = Wrel[idx]; wts[idx] = Wroot[idx]; }
    if (tid < 32) { gbs[tid] = gcnb[tid]; brs[tid] = brel[tid]; }
    if (tid < 128) roff[tid] = 0;
    if (tid < 100) cnt[tid] = 0;
    __syncthreads();
    for (int idx = tid; idx < 1200; idx += 512) {
        const int i = idx / 12, k = idx % 12;
        P[i * 13 + k] = g_h[sids[i] * 12 + k];
    }
    __syncthreads();

    for (int p = tid; p < 10000; p += 512) {
        const int i = p / 100, j = p % 100;
        if (j < i) continue;
        float s = 0.f;
        #pragma unroll
        for (int k = 0; k < 12; k++) s += P[i * 13 + k] * P[j * 13 + k];
        const float v = 1.f / (1.f + __expf(-s));
        D[i * 101 + j] = v;
        D[j * 101 + i] = v;
    }
    __syncthreads();

    // top-16 per row: streaming insertion (stable: strict >, earlier index wins ties)
    if (tid < 100) {
        const float* Drow = D + tid * 101;
        float tv[16]; int tj[16];
        #pragma unroll
        for (int s = 0; s < 16; s++) { tv[s] = -1.f; tj[s] = 0; }
        for (int j = 0; j < 100; j++) {
            const float v = Drow[j];
            if (v > tv[15]) {
                #pragma unroll
                for (int s = 15; s >= 1; s--) {
                    const bool up = (v > tv[s - 1]);
                    const bool here = !up && (v > tv[s]);
                    tv[s] = up ? tv[s - 1] : (here ? v : tv[s]);
                    tj[s] = up ? tj[s - 1] : (here ? j : tj[s]);
                }
                if (v > tv[0]) { tv[0] = v; tj[0] = j; }
            }
        }
        #pragma unroll
        for (int s = 0; s < 16; s++) { Ew[tid * 16 + s] = tv[s]; Ed[tid * 16 + s] = tj[s]; }
    }
    __syncthreads();

    for (int e = tid; e < 1600; e += 512) atomicAdd(&roff[Ed[e] + 1], 1);
    __syncthreads();
    for (int d = 1; d < 128; d <<= 1) {
        int v = 0;
        if (tid < 101 && tid >= d) v = roff[tid - d];
        __syncthreads();
        if (tid < 101) roff[tid] += v;
        __syncthreads();
    }
    for (int e = tid; e < 1600; e += 512) {
        const int d = Ed[e];
        const int slot = atomicAdd(&cnt[d], 1);
        rlist[roff[d] + slot] = e;
    }
    __syncthreads();

    if (tid < 100) {
        float dg = 1.f;
        const int q1 = roff[tid + 1];
        for (int q = roff[tid]; q < q1; q++) dg += Ew[rlist[q]];
        degf[tid] = 1.f / sqrtf(dg);
    }
    __syncthreads();

    for (int idx = tid; idx < 1300; idx += 512) P[idx] = lrelu(P[idx]);
    for (int e = tid; e < 1600; e += 512) coef[e] = Ew[e] * degf[e >> 4];
    __syncthreads();

    const int f  = tid & 31;
    const int c0 = tid >> 5;

    for (int c = c0; c < 100; c += 16) {
        float a = 0.f;
        #pragma unroll
        for (int k = 0; k < 12; k++) a += P[c * 13 + k] * gws[k * 32 + f];
        HW[c * 33 + f] = a;
    }
    __syncthreads();

    for (int c = c0; c < 100; c += 16) {
        float a = 0.f;
        const int q1 = roff[c + 1];
        for (int q = roff[c]; q < q1; q++) {
            const int e = rlist[q];
            a += coef[e] * HW[(e >> 4) * 33 + f];
        }
        const float dc = degf[c];
        GC[c * 33 + f] = gbs[f] + dc * a + dc * dc * HW[c * 33 + f];
    }
    __syncthreads();

    for (int c = c0; c < 100; c += 16) {
        float a = 0.f;
        const int q1 = roff[c + 1];
        for (int q = roff[c]; q < q1; q++) {
            const int e = rlist[q];
            a += Ew[e] * GC[(e >> 4) * 33 + f];
        }
        AGG[c * 33 + f] = a;
    }
    __syncthreads();

    for (int c = c0; c < 100; c += 16) {
        float a = brs[f];
        #pragma unroll
        for (int k = 0; k < 32; k++) a += AGG[c * 33 + k] * wrs[k * 32 + f] + GC[c * 33 + k] * wts[k * 32 + f];
        g_hf[sids[c] * 32 + f] = lrelu(a);
    }
}

// ---------------- host launcher ------------------------------------------
static size_t nn1_smem() {
    return (size_t)(1536 + 16000 + 2000 + 272 + 64 * PH + 1088 + 832 + 832 + 300) * 4;
}
static size_t nn23_smem() {
    return (size_t)((4096 + 16000 + 1000 + 272) + (4864 + 16000 + 1000 + 272)
                    + 64 * PH + 1088 + 2496) * 4;
}
static size_t bin_smem() {
    size_t fl = 1300 + 10100 + 3 * 3300 + 1600 + 1600 + 100 + 384 + 32 + 1024 + 1024 + 32;
    size_t in = 100 + 1600 + 128 + 100 + 1600;
    return (fl + in) * 4;
}

extern "C" void kernel_launch(void* const* d_in, const int* in_sizes, int n_in,
                              void* d_out, int out_size)
{
    const float* x       = (const float*)d_in[0];
    const float* ygen_id = (const float*)d_in[1];
    const float* ygen    = (const float*)d_in[2];
    const float* cb      = (const float*)d_in[3];
    const float* nn1_W1 = (const float*)d_in[4];
    const float* nn1_b1 = (const float*)d_in[5];
    const float* nn1_W2 = (const float*)d_in[6];
    const float* nn1_b2 = (const float*)d_in[7];
    const float* nn1_W3 = (const float*)d_in[8];
    const float* nn1_b3 = (const float*)d_in[9];
    const float* gcn_W  = (const float*)d_in[10];
    const float* gcn_b  = (const float*)d_in[11];
    const float* gc_Wrel  = (const float*)d_in[12];
    const float* gc_brel  = (const float*)d_in[13];
    const float* gc_Wroot = (const float*)d_in[14];
    const float* nn2_W1 = (const float*)d_in[15];
    const float* nn2_b1 = (const float*)d_in[16];
    const float* nn2_W2 = (const float*)d_in[17];
    const float* nn2_b2 = (const float*)d_in[18];
    const float* nn2_W3 = (const float*)d_in[19];
    const float* nn2_b3 = (const float*)d_in[20];
    const float* nn3_W1 = (const float*)d_in[21];
    const float* nn3_b1 = (const float*)d_in[22];
    const float* nn3_W2 = (const float*)d_in[23];
    const float* nn3_b2 = (const float*)d_in[24];
    const float* nn3_W3 = (const float*)d_in[25];
    const float* nn3_b3 = (const float*)d_in[26];

    float* out = (float*)d_out;

    cudaFuncSetAttribute(nn1_kernel,  cudaFuncAttributeMaxDynamicSharedMemorySize, (int)nn1_smem());
    cudaFuncSetAttribute(nn23_kernel, cudaFuncAttributeMaxDynamicSharedMemorySize, (int)nn23_smem());
    cudaFuncSetAttribute(bin_kernel,  cudaFuncAttributeMaxDynamicSharedMemorySize, (int)bin_smem());

    const int grid = (N_NODES + 63) / 64;   // 79

    nn1_kernel<<<grid, 512, nn1_smem()>>>(x, nn1_W1, nn1_b1, nn1_W2, nn1_b2, nn1_W3, nn1_b3, cb);
    sort_kernel<<<NBINS, 256>>>();
    bin_kernel<<<NBINS, 512, bin_smem()>>>(gcn_W, gcn_b, gc_Wrel, gc_brel, gc_Wroot);
    nn23_kernel<<<grid, 512, nn23_smem()>>>(
        nn2_W1, nn2_b1, nn2_W2, nn2_b2, nn2_W3, nn2_b3,
        nn3_W1, nn3_b1, nn3_W2, nn3_b2, nn3_W3, nn3_b3,
        out, out + 30000,
        ygen_id, out + 60000,
        ygen,    out + 90000);
}

// round 16
// speedup vs baseline: 1.2500x; 1.0018x over previous
#include <cuda_runtime.h>
#include <math.h>

#define N_NODES 5000
#define NBINS 50
#define KNN 16
#define SLOPE 0.01f
#define PH 129   // hidden-buffer pitch (129 mod 32 = 1 -> conflict-free)

// ---------------- device scratch ----------------
__device__ float g_h[N_NODES * 12];     // nn1 output (pre-leaky)
__device__ int   g_bin[N_NODES];
__device__ int   g_sorted[N_NODES];     // stable argsort of g_bin
__device__ float g_hf[N_NODES * 32];    // post-conv, post-leaky features

__device__ __forceinline__ float lrelu(float v) { return v > 0.f ? v : SLOPE * v; }

__device__ __forceinline__ unsigned long long pack2(float a, float b) {
    unsigned long long r;
    asm("mov.b64 %0, {%1, %2};" : "=l"(r) : "r"(__float_as_uint(a)), "r"(__float_as_uint(b)));
    return r;
}
__device__ __forceinline__ void unpack2(unsigned long long p, float& a, float& b) {
    unsigned int x, y;
    asm("mov.b64 {%0, %1}, %2;" : "=r"(x), "=r"(y) : "l"(p));
    a = __uint_as_float(x); b = __uint_as_float(y);
}
__device__ __forceinline__ unsigned long long ffma2(unsigned long long a, unsigned long long b, unsigned long long c) {
    unsigned long long d;
    asm("fma.rn.f32x2 %0, %1, %2, %3;" : "=l"(d) : "l"(a), "l"(b), "l"(c));
    return d;
}

// ---------------- MLP machinery (R15 verbatim) -----------------------------
// 512 threads, 64 rows/block (2 rows per lane: lane and lane+32), grid = 79.
// warp w16 = tid>>5: cg = w16 & 7 (16-col slice, j0 = cg*16), kh = w16>>3
// (K-half). Weights staged in smem. K-split partner partials are exchanged
// THROUGH H (kh=1 stores raw partial; bar; kh=0 combines bias+partial+own).

template <int IN, int OUT, int P3>
__device__ __forceinline__ void stage_net(
    const float* __restrict__ W1, const float* __restrict__ b1,
    const float* __restrict__ W2, const float* __restrict__ b2,
    const float* __restrict__ W3, const float* __restrict__ b3,
    float* Ws1, float* Ws2, float* Ws3, float* b1s, float* b2s, float* b3s, int tid)
{
    for (int idx = tid; idx < IN * 128; idx += 512) {
        const int k = idx >> 7, j = idx & 127;
        Ws1[idx] = (j < 125) ? W1[k * 125 + j] : 0.f;
    }
    for (int idx = tid; idx < 125 * 128; idx += 512) {
        const int k = idx >> 7, j = idx & 127;
        Ws2[idx] = (j < 125) ? W2[k * 125 + j] : 0.f;
    }
    for (int idx = tid; idx < 125 * P3; idx += 512) {
        const int k = idx / P3, o = idx % P3;
        Ws3[idx] = (o < OUT) ? W3[k * OUT + o] : 0.f;
    }
    if (tid < 128) {
        b1s[tid] = (tid < 125) ? b1[tid] : 0.f;
        b2s[tid] = (tid < 125) ? b2[tid] : 0.f;
    } else if (tid < 144) {
        const int o = tid - 128;
        b3s[o] = (o < OUT) ? b3[o] : 0.f;
    }
}

// two-row dense: acc[8] per row, weights loaded once per k
template <int K0, int K1>
__device__ __forceinline__ void dense_range2(const float* __restrict__ Ws,
                                             const float* __restrict__ x0,
                                             const float* __restrict__ x1,
                                             int j0,
                                             unsigned long long accA[8],
                                             unsigned long long accB[8])
{
    #pragma unroll 5
    for (int k = K0; k < K1; k++) {
        const float va = x0[k], vb = x1[k];
        const unsigned long long xa = pack2(va, va);
        const unsigned long long xb = pack2(vb, vb);
        const ulonglong2* wp = (const ulonglong2*)(Ws + k * 128 + j0);
        const ulonglong2 wa = wp[0], wb = wp[1], wc = wp[2], wd = wp[3];
        accA[0] = ffma2(xa, wa.x, accA[0]); accA[1] = ffma2(xa, wa.y, accA[1]);
        accA[2] = ffma2(xa, wb.x, accA[2]); accA[3] = ffma2(xa, wb.y, accA[3]);
        accA[4] = ffma2(xa, wc.x, accA[4]); accA[5] = ffma2(xa, wc.y, accA[5]);
        accA[6] = ffma2(xa, wd.x, accA[6]); accA[7] = ffma2(xa, wd.y, accA[7]);
        accB[0] = ffma2(xb, wa.x, accB[0]); accB[1] = ffma2(xb, wa.y, accB[1]);
        accB[2] = ffma2(xb, wb.x, accB[2]); accB[3] = ffma2(xb, wb.y, accB[3]);
        accB[4] = ffma2(xb, wc.x, accB[4]); accB[5] = ffma2(xb, wc.y, accB[5]);
        accB[6] = ffma2(xb, wd.x, accB[6]); accB[7] = ffma2(xb, wd.y, accB[7]);
    }
}

__device__ __forceinline__ void zero8(unsigned long long a[8]) {
    #pragma unroll
    for (int m = 0; m < 8; m++) a[m] = pack2(0.f, 0.f);
}
__device__ __forceinline__ void store_partial(unsigned long long acc[8], float* dst) {
    #pragma unroll
    for (int m = 0; m < 8; m++) {
        float a, b; unpack2(acc[m], a, b);
        dst[2 * m] = a; dst[2 * m + 1] = b;
    }
}
// Pb may alias Hd (per-element read then write is safe)
__device__ __forceinline__ void combine_act(unsigned long long acc[8], const float* __restrict__ bS,
                                            const float* Pb, float* Hd, int j0)
{
    #pragma unroll
    for (int m = 0; m < 8; m++) {
        float a, b; unpack2(acc[m], a, b);
        const int j = j0 + 2 * m;
        const float b0 = (j < 125) ? bS[j] : 0.f;
        const float b1 = (j + 1 < 125) ? bS[j + 1] : 0.f;
        const float p0 = Pb[j], p1 = Pb[j + 1];
        Hd[j]     = lrelu(b0 + a + p0);
        Hd[j + 1] = lrelu(b1 + b + p1);
    }
}

// 3-layer net, K-split + 2 rows/lane, partials exchanged through H.
template <int IN, int OUT, int P3>
__device__ __forceinline__ void run_mlp2h(
    const float* __restrict__ x0, const float* __restrict__ x1,
    const float* Ws1, const float* Ws2, const float* Ws3,
    const float* b1s, const float* b2s, const float* b3s,
    float* H, float* Obuf,
    int lane, int j0, int cg, int kh,
    float& o1A, float& o2A, float& o1B, float& o2B)
{
    unsigned long long accA[8], accB[8];
    float* H0 = H + lane * PH;
    float* H1 = H + (lane + 32) * PH;

    // ---- layer 1 (H not yet live) ----
    zero8(accA); zero8(accB);
    if (kh == 0) dense_range2<0, IN / 2>(Ws1, x0, x1, j0, accA, accB);
    else         dense_range2<IN / 2, IN>(Ws1, x0, x1, j0, accA, accB);
    if (kh == 1) { store_partial(accA, H0 + j0); store_partial(accB, H1 + j0); }
    __syncthreads();
    if (kh == 0) { combine_act(accA, b1s, H0, H0, j0); combine_act(accB, b1s, H1, H1, j0); }
    __syncthreads();

    // ---- layer 2 (K=125) ----
    zero8(accA); zero8(accB);
    if (kh == 0) dense_range2<0, 63>(Ws2, H0, H1, j0, accA, accB);
    else         dense_range2<63, 125>(Ws2, H0, H1, j0, accA, accB);
    __syncthreads();                     // all H reads complete before overwrite
    if (kh == 1) { store_partial(accA, H0 + j0); store_partial(accB, H1 + j0); }
    __syncthreads();
    if (kh == 0) { combine_act(accA, b2s, H0, H0, j0); combine_act(accB, b2s, H1, H1, j0); }
    __syncthreads();

    // ---- layer 3 ----
    const bool c1 = (cg < OUT);
    const bool c2 = (OUT > 8) && (cg + 8 < OUT);
    float a1A = 0.f, a2A = 0.f, a1B = 0.f, a2B = 0.f;
    if (kh == 0) {
        #pragma unroll 7
        for (int k = 0; k < 63; k++) {
            const float hA = H0[k], hB = H1[k];
            if (c1) { a1A += hA * Ws3[k * P3 + cg];     a1B += hB * Ws3[k * P3 + cg]; }
            if (c2) { a2A += hA * Ws3[k * P3 + cg + 8]; a2B += hB * Ws3[k * P3 + cg + 8]; }
        }
    } else {
        #pragma unroll 7
        for (int k = 63; k < 125; k++) {
            const float hA = H0[k], hB = H1[k];
            if (c1) { a1A += hA * Ws3[k * P3 + cg];     a1B += hB * Ws3[k * P3 + cg]; }
            if (c2) { a2A += hA * Ws3[k * P3 + cg + 8]; a2B += hB * Ws3[k * P3 + cg + 8]; }
        }
    }
    if (kh == 1) {
        if (c1) { Obuf[lane * 17 + cg] = a1A;          Obuf[(lane + 32) * 17 + cg] = a1B; }
        if (c2) { Obuf[lane * 17 + cg + 8] = a2A;      Obuf[(lane + 32) * 17 + cg + 8] = a2B; }
    }
    __syncthreads();
    o1A = o2A = o1B = o2B = 0.f;
    if (kh == 0) {
        if (c1) { o1A = b3s[cg] + a1A + Obuf[lane * 17 + cg];
                  o1B = b3s[cg] + a1B + Obuf[(lane + 32) * 17 + cg]; }
        if (c2) { o2A = b3s[cg + 8] + a2A + Obuf[lane * 17 + cg + 8];
                  o2B = b3s[cg + 8] + a2B + Obuf[(lane + 32) * 17 + cg + 8]; }
    }
}

// ---------------- nn1 + fused LSH binning --------------------------------
__global__ __launch_bounds__(512)
void nn1_kernel(const float* __restrict__ x,
                const float* __restrict__ W1, const float* __restrict__ b1,
                const float* __restrict__ W2, const float* __restrict__ b2,
                const float* __restrict__ W3, const float* __restrict__ b3,
                const float* __restrict__ cb)
{
    extern __shared__ float sm[];
    float* Ws1 = sm;                      // 12*128 = 1536
    float* Ws2 = Ws1 + 1536;              // 16000
    float* Ws3 = Ws2 + 16000;             // 125*16 = 2000
    float* b1s = Ws3 + 2000;              // 128
    float* b2s = b1s + 128;               // 128
    float* b3s = b2s + 128;               // 16
    float* H    = b3s + 16;               // 64*PH = 8256
    float* Obuf = H + 64 * PH;            // 1088
    float* xinS = Obuf + 1088;            // 64*13 = 832
    float* HoutS = xinS + 832;            // 832
    float* cbs  = HoutS + 832;            // 300

    const int tid = threadIdx.x;
    stage_net<12, 12, 16>(W1, b1, W2, b2, W3, b3, Ws1, Ws2, Ws3, b1s, b2s, b3s, tid);
    for (int idx = tid; idx < 300; idx += 512) {
        const int k = idx / 25, c = idx % 25;
        cbs[idx] = cb[k * 100 + c];
    }
    for (int idx = tid; idx < 64 * 12; idx += 512) {
        const int r = idx / 12, c = idx % 12;
        const int row = blockIdx.x * 64 + r;
        xinS[r * 13 + c] = (row < N_NODES) ? x[row * 12 + c] : 0.f;
    }
    __syncthreads();

    const int lane = tid & 31;
    const int w16  = tid >> 5;
    const int cg   = w16 & 7;
    const int kh   = w16 >> 3;
    const int j0   = cg * 16;
    const int rowA = blockIdx.x * 64 + lane;
    const int rowB = rowA + 32;

    float o1A, o2A, o1B, o2B;
    run_mlp2h<12, 12, 16>(xinS + lane * 13, xinS + (lane + 32) * 13,
                          Ws1, Ws2, Ws3, b1s, b2s, b3s,
                          H, Obuf, lane, j0, cg, kh, o1A, o2A, o1B, o2B);

    if (kh == 0) {
        if (rowA < N_NODES) g_h[rowA * 12 + cg] = o1A;
        if (rowB < N_NODES) g_h[rowB * 12 + cg] = o1B;
        HoutS[lane * 13 + cg] = o1A;
        HoutS[(lane + 32) * 13 + cg] = o1B;
        if (cg < 4) {
            if (rowA < N_NODES) g_h[rowA * 12 + 8 + cg] = o2A;
            if (rowB < N_NODES) g_h[rowB * 12 + 8 + cg] = o2B;
            HoutS[lane * 13 + 8 + cg] = o2A;
            HoutS[(lane + 32) * 13 + 8 + cg] = o2B;
        }
    }
    __syncthreads();

    if (tid < 64) {
        const int r2 = blockIdx.x * 64 + tid;
        if (r2 < N_NODES) {
            float hr[12];
            #pragma unroll
            for (int k = 0; k < 12; k++) hr[k] = HoutS[tid * 13 + k];
            float mul[25];
            #pragma unroll
            for (int c = 0; c < 25; c++) {
                float s = 0.f;
                #pragma unroll
                for (int k = 0; k < 12; k++) s += hr[k] * cbs[k * 25 + c];
                mul[c] = s;
            }
            float best = -3.4e38f; int bi = 0;
            #pragma unroll
            for (int c = 0; c < 50; c++) {
                const float v = (c < 25) ? mul[c] : -mul[c - 25];
                if (v > best) { best = v; bi = c; }   // first-max: jnp.argmax
            }
            g_bin[r2] = bi;
        }
    }
}

// ---------------- fused nn2 + nn3 (+ passthrough copies) ------------------
__global__ __launch_bounds__(512)
void nn23_kernel(const float* __restrict__ A_W1, const float* __restrict__ A_b1,
                 const float* __restrict__ A_W2, const float* __restrict__ A_b2,
                 const float* __restrict__ A_W3, const float* __restrict__ A_b3,
                 const float* __restrict__ B_W1, const float* __restrict__ B_b1,
                 const float* __restrict__ B_W2, const float* __restrict__ B_b2,
                 const float* __restrict__ B_W3, const float* __restrict__ B_b3,
                 float* __restrict__ cand_ids, float* __restrict__ cand_p4,
                 const float* __restrict__ ygen_id, float* __restrict__ out_yid,
                 const float* __restrict__ ygen,    float* __restrict__ out_yg)
{
    extern __shared__ float sm[];
    float* AWs1 = sm;                     // 32*128 = 4096
    float* AWs2 = AWs1 + 4096;            // 16000
    float* AWs3 = AWs2 + 16000;           // 125*8 = 1000
    float* Ab1  = AWs3 + 1000;            // 128
    float* Ab2  = Ab1 + 128;              // 128
    float* Ab3  = Ab2 + 128;              // 16
    float* BWs1 = Ab3 + 16;               // 38*128 = 4864
    float* BWs2 = BWs1 + 4864;            // 16000
    float* BWs3 = BWs2 + 16000;           // 1000
    float* Bb1  = BWs3 + 1000;            // 128
    float* Bb2  = Bb1 + 128;              // 128
    float* Bb3  = Bb2 + 128;              // 16
    float* H    = Bb3 + 16;               // 64*PH = 8256
    float* Obuf = H + 64 * PH;            // 1088
    float* xinS = Obuf + 1088;            // 64*39 = 2496

    const int tid = threadIdx.x;
    const int gt  = blockIdx.x * 512 + tid;
    if (gt < 30000) { out_yid[gt] = ygen_id[gt]; out_yg[gt] = ygen[gt]; }

    stage_net<32, 6, 8>(A_W1, A_b1, A_W2, A_b2, A_W3, A_b3, AWs1, AWs2, AWs3, Ab1, Ab2, Ab3, tid);
    stage_net<38, 6, 8>(B_W1, B_b1, B_W2, B_b2, B_W3, B_b3, BWs1, BWs2, BWs3, Bb1, Bb2, Bb3, tid);
    for (int idx = tid; idx < 64 * 32; idx += 512) {
        const int r = idx >> 5, c = idx & 31;
        const int row = blockIdx.x * 64 + r;
        xinS[r * 39 + c] = (row < N_NODES) ? g_hf[row * 32 + c] : 0.f;
    }
    __syncthreads();

    const int lane = tid & 31;
    const int w16  = tid >> 5;
    const int cg   = w16 & 7;
    const int kh   = w16 >> 3;
    const int j0   = cg * 16;
    const int rowA = blockIdx.x * 64 + lane;
    const int rowB = rowA + 32;

    float o1A, o2A, o1B, o2B;
    run_mlp2h<32, 6, 8>(xinS + lane * 39, xinS + (lane + 32) * 39,
                        AWs1, AWs2, AWs3, Ab1, Ab2, Ab3,
                        H, Obuf, lane, j0, cg, kh, o1A, o2A, o1B, o2B);

    if (kh == 0 && cg < 6) {
        if (rowA < N_NODES) cand_ids[rowA * 6 + cg] = o1A;
        if (rowB < N_NODES) cand_ids[rowB * 6 + cg] = o1B;
        xinS[lane * 39 + 32 + cg] = o1A;
        xinS[(lane + 32) * 39 + 32 + cg] = o1B;
    }
    __syncthreads();

    run_mlp2h<38, 6, 8>(xinS + lane * 39, xinS + (lane + 32) * 39,
                        BWs1, BWs2, BWs3, Bb1, Bb2, Bb3,
                        H, Obuf, lane, j0, cg, kh, o1A, o2A, o1B, o2B);

    if (kh == 0 && cg < 6) {
        if (rowA < N_NODES) cand_p4[rowA * 6 + cg] = o1A;
        if (rowB < N_NODES) cand_p4[rowB * 6 + cg] = o1B;
    }
}

// ---------------- stable counting-sort (verbatim) --------------------------
__global__ __launch_bounds__(256, 1) void sort_kernel()
{
    __shared__ int cB[8], cL[8];
    const int b = blockIdx.x;
    const int w = threadIdx.x >> 5, lane = threadIdx.x & 31;
    const int beg = w * 625, end = beg + 625;

    int nB = 0, nL = 0;
    for (int i0 = beg; i0 < end; i0 += 32) {
        const int i = i0 + lane;
        const bool inr = i < end;
        const int bv = inr ? g_bin[i] : 0x7fffffff;
        nB += __popc(__ballot_sync(0xffffffffu, inr && bv == b));
        nL += __popc(__ballot_sync(0xffffffffu, inr && bv <  b));
    }
    if (lane == 0) { cB[w] = nB; cL[w] = nL; }
    __syncthreads();

    int off = 0;
    #pragma unroll
    for (int q = 0; q < 8; q++) off += cL[q];
    for (int q = 0; q < w; q++) off += cB[q];

    for (int i0 = beg; i0 < end; i0 += 32) {
        const int i = i0 + lane;
        const bool inr = i < end;
        const int bv = inr ? g_bin[i] : 0x7fffffff;
        const bool p = inr && bv == b;
        const unsigned m = __ballot_sync(0xffffffffu, p);
        if (p) g_sorted[off + __popc(m & ((1u << lane) - 1u))] = i;
        off += __popc(m);
    }
}

// ---------------- per-chunk graph kernel (R15 algorithm, 1024 threads) ----
__global__ __launch_bounds__(1024, 1)
void bin_kernel(const float* __restrict__ gcnW, const float* __restrict__ gcnb,
                const float* __restrict__ Wrel, const float* __restrict__ brel,
                const float* __restrict__ Wroot)
{
    extern __shared__ float sm[];
    float* P    = sm;                   // 100 x 13
    float* D    = P + 1300;             // 100 x 101
    float* HW   = D + 10100;            // 100 x 33
    float* GC   = HW + 3300;
    float* AGG  = GC + 3300;
    float* Ew   = AGG + 3300;           // 1600
    float* coef = Ew + 1600;            // 1600
    float* degf = coef + 1600;          // 100
    float* gws  = degf + 100;           // 384
    float* gbs  = gws + 384;            // 32
    float* wrs  = gbs + 32;             // 1024
    float* wts  = wrs + 1024;           // 1024
    float* brs  = wts + 1024;           // 32
    int* sids  = (int*)(brs + 32);      // 100
    int* Ed    = sids + 100;            // 1600
    int* roff  = Ed + 1600;             // 128
    int* cnt   = roff + 128;            // 100
    int* rlist = cnt + 100;             // 1600

    const int tid = threadIdx.x;
    const int b = blockIdx.x;

    if (tid < 100) sids[tid] = g_sorted[b * 100 + tid];
    for (int idx = tid; idx < 384; idx += 1024) gws[idx] = gcnW[idx];
    for (int idx = tid; idx < 1024; idx += 1024) { wrs[idx] = Wrel[idx]; wts[idx] = Wroot[idx]; }
    if (tid < 32) { gbs[tid] = gcnb[tid]; brs[tid] = brel[tid]; }
    if (tid < 128) roff[tid] = 0;
    if (tid < 100) cnt[tid] = 0;
    __syncthreads();
    for (int idx = tid; idx < 1200; idx += 1024) {
        const int i = idx / 12, k = idx % 12;
        P[i * 13 + k] = g_h[sids[i] * 12 + k];
    }
    __syncthreads();

    for (int p = tid; p < 10000; p += 1024) {
        const int i = p / 100, j = p % 100;
        if (j < i) continue;
        float s = 0.f;
        #pragma unroll
        for (int k = 0; k < 12; k++) s += P[i * 13 + k] * P[j * 13 + k];
        const float v = 1.f / (1.f + __expf(-s));
        D[i * 101 + j] = v;
        D[j * 101 + i] = v;
    }
    __syncthreads();

    // top-16 per row: streaming insertion (stable: strict >, earlier index wins ties)
    if (tid < 100) {
        const float* Drow = D + tid * 101;
        float tv[16]; int tj[16];
        #pragma unroll
        for (int s = 0; s < 16; s++) { tv[s] = -1.f; tj[s] = 0; }
        for (int j = 0; j < 100; j++) {
            const float v = Drow[j];
            if (v > tv[15]) {
                #pragma unroll
                for (int s = 15; s >= 1; s--) {
                    const bool up = (v > tv[s - 1]);
                    const bool here = !up && (v > tv[s]);
                    tv[s] = up ? tv[s - 1] : (here ? v : tv[s]);
                    tj[s] = up ? tj[s - 1] : (here ? j : tj[s]);
                }
                if (v > tv[0]) { tv[0] = v; tj[0] = j; }
            }
        }
        #pragma unroll
        for (int s = 0; s < 16; s++) { Ew[tid * 16 + s] = tv[s]; Ed[tid * 16 + s] = tj[s]; }
    }
    __syncthreads();

    for (int e = tid; e < 1600; e += 1024) atomicAdd(&roff[Ed[e] + 1], 1);
    __syncthreads();
    for (int d = 1; d < 128; d <<= 1) {
        int v = 0;
        if (tid < 101 && tid >= d) v = roff[tid - d];
        __syncthreads();
        if (tid < 101) roff[tid] += v;
        __syncthreads();
    }
    for (int e = tid; e < 1600; e += 1024) {
        const int d = Ed[e];
        const int slot = atomicAdd(&cnt[d], 1);
        rlist[roff[d] + slot] = e;
    }
    __syncthreads();

    if (tid < 100) {
        float dg = 1.f;
        const int q1 = roff[tid + 1];
        for (int q = roff[tid]; q < q1; q++) dg += Ew[rlist[q]];
        degf[tid] = 1.f / sqrtf(dg);
    }
    __syncthreads();

    for (int idx = tid; idx < 1300; idx += 1024) P[idx] = lrelu(P[idx]);
    for (int e = tid; e < 1600; e += 1024) coef[e] = Ew[e] * degf[e >> 4];
    __syncthreads();

    const int f  = tid & 31;
    const int c0 = tid >> 5;     // 32 row groups

    for (int c = c0; c < 100; c += 32) {
        float a = 0.f;
        #pragma unroll
        for (int k = 0; k < 12; k++) a += P[c * 13 + k] * gws[k * 32 + f];
        HW[c * 33 + f] = a;
    }
    __syncthreads();

    for (int c = c0; c < 100; c += 32) {
        float a = 0.f;
        const int q1 = roff[c + 1];
        for (int q = roff[c]; q < q1; q++) {
            const int e = rlist[q];
            a += coef[e] * HW[(e >> 4) * 33 + f];
        }
        const float dc = degf[c];
        GC[c * 33 + f] = gbs[f] + dc * a + dc * dc * HW[c * 33 + f];
    }
    __syncthreads();

    for (int c = c0; c < 100; c += 32) {
        float a = 0.f;
        const int q1 = roff[c + 1];
        for (int q = roff[c]; q < q1; q++) {
            const int e = rlist[q];
            a += Ew[e] * GC[(e >> 4) * 33 + f];
        }
        AGG[c * 33 + f] = a;
    }
    __syncthreads();

    for (int c = c0; c < 100; c += 32) {
        float a = brs[f];
        #pragma unroll
        for (int k = 0; k < 32; k++) a += AGG[c * 33 + k] * wrs[k * 32 + f] + GC[c * 33 + k] * wts[k * 32 + f];
        g_hf[sids[c] * 32 + f] = lrelu(a);
    }
}

// ---------------- host launcher ------------------------------------------
static size_t nn1_smem() {
    return (size_t)(1536 + 16000 + 2000 + 272 + 64 * PH + 1088 + 832 + 832 + 300) * 4;
}
static size_t nn23_smem() {
    return (size_t)((4096 + 16000 + 1000 + 272) + (4864 + 16000 + 1000 + 272)
                    + 64 * PH + 1088 + 2496) * 4;
}
static size_t bin_smem() {
    size_t fl = 1300 + 10100 + 3 * 3300 + 1600 + 1600 + 100 + 384 + 32 + 1024 + 1024 + 32;
    size_t in = 100 + 1600 + 128 + 100 + 1600;
    return (fl + in) * 4;
}

extern "C" void kernel_launch(void* const* d_in, const int* in_sizes, int n_in,
                              void* d_out, int out_size)
{
    const float* x       = (const float*)d_in[0];
    const float* ygen_id = (const float*)d_in[1];
    const float* ygen    = (const float*)d_in[2];
    const float* cb      = (const float*)d_in[3];
    const float* nn1_W1 = (const float*)d_in[4];
    const float* nn1_b1 = (const float*)d_in[5];
    const float* nn1_W2 = (const float*)d_in[6];
    const float* nn1_b2 = (const float*)d_in[7];
    const float* nn1_W3 = (const float*)d_in[8];
    const float* nn1_b3 = (const float*)d_in[9];
    const float* gcn_W  = (const float*)d_in[10];
    const float* gcn_b  = (const float*)d_in[11];
    const float* gc_Wrel  = (const float*)d_in[12];
    const float* gc_brel  = (const float*)d_in[13];
    const float* gc_Wroot = (const float*)d_in[14];
    const float* nn2_W1 = (const float*)d_in[15];
    const float* nn2_b1 = (const float*)d_in[16];
    const float* nn2_W2 = (const float*)d_in[17];
    const float* nn2_b2 = (const float*)d_in[18];
    const float* nn2_W3 = (const float*)d_in[19];
    const float* nn2_b3 = (const float*)d_in[20];
    const float* nn3_W1 = (const float*)d_in[21];
    const float* nn3_b1 = (const float*)d_in[22];
    const float* nn3_W2 = (const float*)d_in[23];
    const float* nn3_b2 = (const float*)d_in[24];
    const float* nn3_W3 = (const float*)d_in[25];
    const float* nn3_b3 = (const float*)d_in[26];

    float* out = (float*)d_out;

    cudaFuncSetAttribute(nn1_kernel,  cudaFuncAttributeMaxDynamicSharedMemorySize, (int)nn1_smem());
    cudaFuncSetAttribute(nn23_kernel, cudaFuncAttributeMaxDynamicSharedMemorySize, (int)nn23_smem());
    cudaFuncSetAttribute(bin_kernel,  cudaFuncAttributeMaxDynamicSharedMemorySize, (int)bin_smem());

    const int grid = (N_NODES + 63) / 64;   // 79

    nn1_kernel<<<grid, 512, nn1_smem()>>>(x, nn1_W1, nn1_b1, nn1_W2, nn1_b2, nn1_W3, nn1_b3, cb);
    sort_kernel<<<NBINS, 256>>>();
    bin_kernel<<<NBINS, 1024, bin_smem()>>>(gcn_W, gcn_b, gc_Wrel, gc_brel, gc_Wroot);
    nn23_kernel<<<grid, 512, nn23_smem()>>>(
        nn2_W1, nn2_b1, nn2_W2, nn2_b2, nn2_W3, nn2_b3,
        nn3_W1, nn3_b1, nn3_W2, nn3_b2, nn3_W3, nn3_b3,
        out, out + 30000,
        ygen_id, out + 60000,
        ygen,    out + 90000);
}